// round 9
// baseline (speedup 1.0000x reference)
#include <cuda_runtime.h>
#include <cuda_fp16.h>
#include <stdint.h>
#include <math.h>

#define B 2
#define S 2048
#define H 1024
#define NH 16
#define HD 64
#define BH 4
#define BD 256
#define MS (B*S)   /* 4096 rows */
#define MHH (H*H)  /* 1048576 */

// ---------------- scratch (static device globals; no allocations) ----------------
__device__ __half g_Q[MS * H];
__device__ __half g_K[MS * H];
__device__ __half g_V[MS * H];
__device__ float  g_MOD[MS * NH];
__device__ float  g_CTX[MS * H];
__device__ __half g_QKV3[MS * 3 * H];
__device__ __half g_T1[MS * H];
__device__ __half g_HSh[MS * H];       // hs in half
__device__ __half g_WH[12 * MHH];      // all weights in half

// ---------------- helpers ----------------
__device__ __forceinline__ uint32_t cvta_s(const void* p) {
    return (uint32_t)__cvta_generic_to_shared(p);
}
__device__ __forceinline__ uint32_t packh2(float a, float b) {
    __half2 h = __floats2half2_rn(a, b);
    return *reinterpret_cast<uint32_t*>(&h);
}
__device__ __forceinline__ void ldsm_x4(uint32_t addr, uint32_t* r) {
    asm volatile("ldmatrix.sync.aligned.m8n8.x4.shared.b16 {%0,%1,%2,%3}, [%4];"
        : "=r"(r[0]), "=r"(r[1]), "=r"(r[2]), "=r"(r[3]) : "r"(addr));
}
__device__ __forceinline__ void ldsm_x4_t(uint32_t addr, uint32_t* r) {
    asm volatile("ldmatrix.sync.aligned.m8n8.x4.trans.shared.b16 {%0,%1,%2,%3}, [%4];"
        : "=r"(r[0]), "=r"(r[1]), "=r"(r[2]), "=r"(r[3]) : "r"(addr));
}
__device__ __forceinline__ void ldsm_x2(uint32_t addr, uint32_t* r) {
    asm volatile("ldmatrix.sync.aligned.m8n8.x2.shared.b16 {%0,%1}, [%2];"
        : "=r"(r[0]), "=r"(r[1]) : "r"(addr));
}
__device__ __forceinline__ void mma_f16(float* d, const uint32_t* a, const uint32_t* b) {
    asm volatile(
        "mma.sync.aligned.m16n8k16.row.col.f32.f16.f16.f32 "
        "{%0,%1,%2,%3}, {%4,%5,%6,%7}, {%8,%9}, {%0,%1,%2,%3};"
        : "+f"(d[0]), "+f"(d[1]), "+f"(d[2]), "+f"(d[3])
        : "r"(a[0]), "r"(a[1]), "r"(a[2]), "r"(a[3]), "r"(b[0]), "r"(b[1]));
}

// ---------------- fused fp32 -> fp16 converts (single launch) ----------------
struct CvtJobs {
    const float* src[9];
    __half* dst[9];
    int start[10];   // block-range prefix (2048 elems per block, all sizes divisible)
};

__global__ __launch_bounds__(256) void cvt_all(CvtJobs j)
{
    int b = blockIdx.x;
    int k = 0;
#pragma unroll
    for (int i = 0; i < 8; i++) if (b >= j.start[i + 1]) k = i + 1;
    int off = (b - j.start[k]) * 2048 + threadIdx.x * 8;
    const float* src = j.src[k];
    __half* dst = j.dst[k];
    float4 a = *(const float4*)(src + off);
    float4 c = *(const float4*)(src + off + 4);
    uint4 o;
    o.x = packh2(a.x, a.y); o.y = packh2(a.z, a.w);
    o.z = packh2(c.x, c.y); o.w = packh2(c.z, c.w);
    *(uint4*)(dst + off) = o;
}

// ---------------- FP16 tensor-core GEMM (half W; templated A/out; opt blend) ----------------
template<typename TA, typename TO, bool BLEND>
__global__ __launch_bounds__(256) void gemm_tc(
    const TA* __restrict__ A, const __half* __restrict__ W,
    const float* __restrict__ bias, TO* __restrict__ C,
    int M, int N, int K,
    const float* __restrict__ bld, float wa, float wb)
{
    __shared__ __half As[128][40];    // row stride 80B
    __shared__ __half Bs[32][136];    // row stride 272B

    int tid = threadIdx.x, warp = tid >> 5, lane = tid & 31;
    int wm = (warp >> 2) * 64, wn = (warp & 3) * 32;
    int m0 = blockIdx.y * 128, n0 = blockIdx.x * 128;
    int gid = lane >> 2, tig = lane & 3;

    float acc[4][4][4];
#pragma unroll
    for (int mt = 0; mt < 4; mt++)
#pragma unroll
        for (int nt = 0; nt < 4; nt++)
#pragma unroll
            for (int r = 0; r < 4; r++) acc[mt][nt][r] = 0.f;

    int aRow[4], aCol[4], bRow[4], bCol[4];
#pragma unroll
    for (int i = 0; i < 4; i++) {
        int fi = tid + 256 * i;
        aRow[i] = fi >> 3;  aCol[i] = (fi & 7) * 4;
        bRow[i] = fi >> 5;  bCol[i] = (fi & 31) * 4;
    }

    int lr = ((lane >> 3) & 1) * 8 + (lane & 7);
    int lc = (lane >> 4) * 8;
    uint32_t a_addr[4], b_addr[2];
#pragma unroll
    for (int mt = 0; mt < 4; mt++)
        a_addr[mt] = cvta_s(&As[wm + mt * 16 + lr][lc]);
#pragma unroll
    for (int ntp = 0; ntp < 2; ntp++)
        b_addr[ntp] = cvta_s(&Bs[lr][wn + ntp * 16 + lc]);

    uint2 aPk[4], bPk[4];
#pragma unroll
    for (int i = 0; i < 4; i++) {
        if constexpr (sizeof(TA) == 4) {
            float4 av = *(const float4*)((const float*)A + (size_t)(m0 + aRow[i]) * K + aCol[i]);
            aPk[i].x = packh2(av.x, av.y); aPk[i].y = packh2(av.z, av.w);
        } else {
            aPk[i] = *(const uint2*)((const __half*)A + (size_t)(m0 + aRow[i]) * K + aCol[i]);
        }
        bPk[i] = *(const uint2*)(W + (size_t)bRow[i] * N + n0 + bCol[i]);
    }
#pragma unroll
    for (int i = 0; i < 4; i++) {
        *(uint2*)&As[aRow[i]][aCol[i]] = aPk[i];
        *(uint2*)&Bs[bRow[i]][bCol[i]] = bPk[i];
    }
    __syncthreads();

    int ntiles = K / 32;
    for (int kt = 0; kt < ntiles; kt++) {
        if (kt + 1 < ntiles) {
            int kb = (kt + 1) * 32;
#pragma unroll
            for (int i = 0; i < 4; i++) {
                if constexpr (sizeof(TA) == 4) {
                    float4 av = *(const float4*)((const float*)A + (size_t)(m0 + aRow[i]) * K + kb + aCol[i]);
                    aPk[i].x = packh2(av.x, av.y); aPk[i].y = packh2(av.z, av.w);
                } else {
                    aPk[i] = *(const uint2*)((const __half*)A + (size_t)(m0 + aRow[i]) * K + kb + aCol[i]);
                }
                bPk[i] = *(const uint2*)(W + (size_t)(kb + bRow[i]) * N + n0 + bCol[i]);
            }
        }
#pragma unroll
        for (int q = 0; q < 2; q++) {
            int kq = q * 16;
            uint32_t af[4][4], bu0[4], bu1[4];
#pragma unroll
            for (int mt = 0; mt < 4; mt++) ldsm_x4(a_addr[mt] + kq * 2, af[mt]);
            ldsm_x4_t(b_addr[0] + kq * 272, bu0);
            ldsm_x4_t(b_addr[1] + kq * 272, bu1);
#pragma unroll
            for (int mt = 0; mt < 4; mt++) {
                mma_f16(acc[mt][0], af[mt], bu0 + 0);
                mma_f16(acc[mt][1], af[mt], bu0 + 2);
                mma_f16(acc[mt][2], af[mt], bu1 + 0);
                mma_f16(acc[mt][3], af[mt], bu1 + 2);
            }
        }
        __syncthreads();
        if (kt + 1 < ntiles) {
#pragma unroll
            for (int i = 0; i < 4; i++) {
                *(uint2*)&As[aRow[i]][aCol[i]] = aPk[i];
                *(uint2*)&Bs[bRow[i]][bCol[i]] = bPk[i];
            }
            __syncthreads();
        }
    }

#pragma unroll
    for (int mt = 0; mt < 4; mt++) {
        int r0 = m0 + wm + mt * 16 + gid;
#pragma unroll
        for (int nt = 0; nt < 4; nt++) {
            int c = n0 + wn + nt * 8 + tig * 2;
            float b0v = bias[c], b1v = bias[c + 1];
            float e00 = acc[mt][nt][0] + b0v, e01 = acc[mt][nt][1] + b1v;
            float e10 = acc[mt][nt][2] + b0v, e11 = acc[mt][nt][3] + b1v;
            if constexpr (BLEND) {
                float2 x0 = *(const float2*)(bld + (size_t)r0 * N + c);
                float2 x1 = *(const float2*)(bld + (size_t)(r0 + 8) * N + c);
                e00 = x0.x * wa + e00 * wb; e01 = x0.y * wa + e01 * wb;
                e10 = x1.x * wa + e10 * wb; e11 = x1.y * wa + e11 * wb;
            }
            if constexpr (sizeof(TO) == 2) {
                *(uint32_t*)((__half*)C + (size_t)r0 * N + c) = packh2(e00, e01);
                *(uint32_t*)((__half*)C + (size_t)(r0 + 8) * N + c) = packh2(e10, e11);
            } else {
                float2 v0, v1;
                v0.x = e00; v0.y = e01; v1.x = e10; v1.y = e11;
                *(float2*)((float*)C + (size_t)r0 * N + c) = v0;
                *(float2*)((float*)C + (size_t)(r0 + 8) * N + c) = v1;
            }
        }
    }
}

// ---------------- modulation (smem-tiled): sigmoid(hs@Wg + bg + cvec@Wa + ba) ----------------
__global__ __launch_bounds__(256) void gatemod2(
    const float* __restrict__ hs, const float* __restrict__ Wg,
    const float* __restrict__ bg, const float* __restrict__ cvec,
    const float* __restrict__ Wa, const float* __restrict__ ba,
    float* __restrict__ MODo)
{
    __shared__ float Wgs[64][16];
    __shared__ float hss[16][68];
    __shared__ float awS[16];

    int tid = threadIdx.x;
    int m0 = blockIdx.x * 16;
    int r = tid >> 4, n = tid & 15;

    if (tid < 16) {
        float aw = ba[tid] + bg[tid];
#pragma unroll
        for (int k = 0; k < 16; k++) aw += cvec[k] * Wa[k * 16 + tid];
        awS[tid] = aw;
    }

    float acc = 0.f;
    for (int kt = 0; kt < H; kt += 64) {
        __syncthreads();
        *(float4*)&((float*)Wgs)[tid * 4] = *(const float4*)&Wg[kt * 16 + tid * 4];
        int r2 = tid >> 4, k2 = (tid & 15) * 4;
        *(float4*)&hss[r2][k2] = *(const float4*)&hs[(size_t)(m0 + r2) * H + kt + k2];
        __syncthreads();
#pragma unroll
        for (int k = 0; k < 64; k++) acc += hss[r][k] * Wgs[k][n];
    }
    float x = acc + awS[n];
    MODo[(size_t)(m0 + r) * NH + n] = 1.f / (1.f + __expf(-x));
}

// ---------------- main attention (fp16 TC): 16 heads, hd=64, 64-key tiles ----------------
// 128 q/block, 8 warps x 16 rows; K-tile 64 processed as two 32-key halves (no inner syncs)
__global__ __launch_bounds__(256) void attn_main_f16(
    const __half* __restrict__ Qb, const __half* __restrict__ Kb,
    const __half* __restrict__ Vb, const float* __restrict__ MODb,
    const int* __restrict__ maskb, float* __restrict__ Ob)
{
    __shared__ __half Ks[64][72];   // [key][d], 144B stride
    __shared__ __half Vs[64][72];
    __shared__ float Madd[64];

    int tid = threadIdx.x, lane = tid & 31, warp = tid >> 5;
    int gid = lane >> 2, tig = lane & 3;
    int q0 = blockIdx.x * 128, h = blockIdx.y, b = blockIdx.z;
    int qw = q0 + warp * 16;

    uint32_t qf[4][4];
    const __half* Qg = Qb + (size_t)(b * S + qw) * H + h * HD;
#pragma unroll
    for (int s = 0; s < 4; s++) {
        int c0 = s * 16 + 2 * tig;
        qf[s][0] = *(const uint32_t*)(Qg + (size_t)gid * H + c0);
        qf[s][1] = *(const uint32_t*)(Qg + (size_t)(gid + 8) * H + c0);
        qf[s][2] = *(const uint32_t*)(Qg + (size_t)gid * H + c0 + 8);
        qf[s][3] = *(const uint32_t*)(Qg + (size_t)(gid + 8) * H + c0 + 8);
    }
    float mod0 = MODb[(size_t)(b * S + qw + gid) * NH + h] * 0.125f;
    float mod1 = MODb[(size_t)(b * S + qw + gid + 8) * NH + h] * 0.125f;

    uint32_t kaddr[2], vaddr[4];
#pragma unroll
    for (int ntp = 0; ntp < 2; ntp++)
        kaddr[ntp] = cvta_s(&Ks[(ntp * 2 + (lane >> 4)) * 8 + (lane & 7)][((lane >> 3) & 1) * 8]);
#pragma unroll
    for (int nfp = 0; nfp < 4; nfp++)
        vaddr[nfp] = cvta_s(&Vs[((lane >> 3) & 1) * 8 + (lane & 7)][(nfp * 2 + (lane >> 4)) * 8]);

    int cr = tid >> 3, cs = (tid & 7) * 8;
    const __half* KgB = Kb + (size_t)(b * S) * H + h * HD;
    const __half* VgB = Vb + (size_t)(b * S) * H + h * HD;

    float m0v = -1e30f, m1v = -1e30f, l0 = 0.f, l1 = 0.f;
    float oacc[8][4];
#pragma unroll
    for (int nf = 0; nf < 8; nf++)
#pragma unroll
        for (int r = 0; r < 4; r++) oacc[nf][r] = 0.f;

    for (int kt = 0; kt < S; kt += 64) {
        __syncthreads();
#pragma unroll
        for (int it = 0; it < 2; it++) {
            int row = cr + it * 32;
            *(uint4*)&Ks[row][cs] = *(const uint4*)(KgB + (size_t)(kt + row) * H + cs);
            *(uint4*)&Vs[row][cs] = *(const uint4*)(VgB + (size_t)(kt + row) * H + cs);
        }
        if (tid < 64) Madd[tid] = maskb[b * S + kt + tid] ? 0.f : -1e30f;
        __syncthreads();

#pragma unroll
        for (int half = 0; half < 2; half++) {
            uint32_t so = (uint32_t)half * 4608;   // 32 rows * 144B
            int mo = half * 32;

            float sc[4][4];
#pragma unroll
            for (int nf = 0; nf < 4; nf++)
#pragma unroll
                for (int r = 0; r < 4; r++) sc[nf][r] = 0.f;
#pragma unroll
            for (int s = 0; s < 4; s++) {
                uint32_t ku0[4], ku1[4];
                ldsm_x4(kaddr[0] + so + s * 32, ku0);
                ldsm_x4(kaddr[1] + so + s * 32, ku1);
                mma_f16(sc[0], qf[s], ku0 + 0);
                mma_f16(sc[1], qf[s], ku0 + 2);
                mma_f16(sc[2], qf[s], ku1 + 0);
                mma_f16(sc[3], qf[s], ku1 + 2);
            }

            float mx0 = -1e30f, mx1 = -1e30f;
#pragma unroll
            for (int nf = 0; nf < 4; nf++) {
                float ma = Madd[mo + nf * 8 + 2 * tig], mb2 = Madd[mo + nf * 8 + 2 * tig + 1];
                sc[nf][0] = sc[nf][0] * mod0 + ma;
                sc[nf][1] = sc[nf][1] * mod0 + mb2;
                sc[nf][2] = sc[nf][2] * mod1 + ma;
                sc[nf][3] = sc[nf][3] * mod1 + mb2;
                mx0 = fmaxf(mx0, fmaxf(sc[nf][0], sc[nf][1]));
                mx1 = fmaxf(mx1, fmaxf(sc[nf][2], sc[nf][3]));
            }
            mx0 = fmaxf(mx0, __shfl_xor_sync(0xffffffffu, mx0, 1));
            mx0 = fmaxf(mx0, __shfl_xor_sync(0xffffffffu, mx0, 2));
            mx1 = fmaxf(mx1, __shfl_xor_sync(0xffffffffu, mx1, 1));
            mx1 = fmaxf(mx1, __shfl_xor_sync(0xffffffffu, mx1, 2));
            float mn0 = fmaxf(m0v, mx0), mn1 = fmaxf(m1v, mx1);
            float al0 = __expf(m0v - mn0), al1 = __expf(m1v - mn1);
            float ps0 = 0.f, ps1 = 0.f;
            uint32_t pva[2][4];
#pragma unroll
            for (int nf = 0; nf < 4; nf++) {
                float p00 = __expf(sc[nf][0] - mn0), p01 = __expf(sc[nf][1] - mn0);
                float p10 = __expf(sc[nf][2] - mn1), p11 = __expf(sc[nf][3] - mn1);
                ps0 += p00 + p01; ps1 += p10 + p11;
                int s2 = nf >> 1, hi = (nf & 1) * 2;
                pva[s2][hi]     = packh2(p00, p01);
                pva[s2][hi + 1] = packh2(p10, p11);
            }
            ps0 += __shfl_xor_sync(0xffffffffu, ps0, 1);
            ps0 += __shfl_xor_sync(0xffffffffu, ps0, 2);
            ps1 += __shfl_xor_sync(0xffffffffu, ps1, 1);
            ps1 += __shfl_xor_sync(0xffffffffu, ps1, 2);
            l0 = l0 * al0 + ps0; l1 = l1 * al1 + ps1;
            m0v = mn0; m1v = mn1;
#pragma unroll
            for (int nf = 0; nf < 8; nf++) {
                oacc[nf][0] *= al0; oacc[nf][1] *= al0;
                oacc[nf][2] *= al1; oacc[nf][3] *= al1;
            }

#pragma unroll
            for (int s2 = 0; s2 < 2; s2++) {
#pragma unroll
                for (int nfp = 0; nfp < 4; nfp++) {
                    uint32_t vu[4];
                    ldsm_x4_t(vaddr[nfp] + so + s2 * 16 * 144, vu);
                    mma_f16(oacc[nfp * 2],     pva[s2], vu + 0);
                    mma_f16(oacc[nfp * 2 + 1], pva[s2], vu + 2);
                }
            }
        }
    }

    float inv0 = 1.f / l0, inv1 = 1.f / l1;
    float* Og = Ob + (size_t)(b * S + qw) * H + h * HD;
#pragma unroll
    for (int nf = 0; nf < 8; nf++) {
        int c = nf * 8 + 2 * tig;
        float2 v0, v1;
        v0.x = oacc[nf][0] * inv0; v0.y = oacc[nf][1] * inv0;
        v1.x = oacc[nf][2] * inv1; v1.y = oacc[nf][3] * inv1;
        *(float2*)(Og + (size_t)gid * H + c) = v0;
        *(float2*)(Og + (size_t)(gid + 8) * H + c) = v1;
    }
}

// ---------------- big-head attention (fp16 TC): 4 heads, hd=256 ----------------
__global__ __launch_bounds__(256) void attn_big_f16(
    const __half* __restrict__ Qb, const __half* __restrict__ Kb,
    const __half* __restrict__ Vb, int ld, __half* __restrict__ Ob, float scale)
{
    __shared__ __half Ks[32][264];   // [key][d], 528B stride
    __shared__ __half Vs[32][264];
    __shared__ float SP[32][36];
    __shared__ __half SPh[32][40];
    __shared__ float Mst[32], Lst[32], Alp[32];

    int tid = threadIdx.x, lane = tid & 31, warp = tid >> 5;
    int gid = lane >> 2, tig = lane & 3;
    int wm = warp >> 2, wn = warp & 3;
    int q0 = blockIdx.x * 32, h = blockIdx.y, b = blockIdx.z;

    uint32_t qf[16][4];
    const __half* Qg = Qb + (size_t)(b * S + q0 + wm * 16) * ld + h * BD;
#pragma unroll
    for (int s = 0; s < 16; s++) {
        int c0 = s * 16 + 2 * tig;
        qf[s][0] = *(const uint32_t*)(Qg + (size_t)gid * ld + c0);
        qf[s][1] = *(const uint32_t*)(Qg + (size_t)(gid + 8) * ld + c0);
        qf[s][2] = *(const uint32_t*)(Qg + (size_t)gid * ld + c0 + 8);
        qf[s][3] = *(const uint32_t*)(Qg + (size_t)(gid + 8) * ld + c0 + 8);
    }
    if (tid < 32) { Mst[tid] = -1e30f; Lst[tid] = 0.f; }

    uint32_t kaddr = cvta_s(&Ks[wn * 8 + (lane & 7)][((lane >> 3) & 1) * 8]);
    uint32_t paddr = cvta_s(&SPh[wm * 16 + ((lane >> 3) & 1) * 8 + (lane & 7)][(lane >> 4) * 8]);
    uint32_t vaddr = cvta_s(&Vs[((lane >> 3) & 1) * 8 + (lane & 7)][wn * 64 + (lane >> 4) * 8]);

    const __half* KgB = Kb + (size_t)(b * S) * ld + h * BD;
    const __half* VgB = Vb + (size_t)(b * S) * ld + h * BD;

    float oacc[8][4];
#pragma unroll
    for (int nf = 0; nf < 8; nf++)
#pragma unroll
        for (int r = 0; r < 4; r++) oacc[nf][r] = 0.f;

    for (int kt = 0; kt < S; kt += 32) {
        __syncthreads();
#pragma unroll
        for (int it = 0; it < 4; it++) {
            int idx = tid + it * 256;
            int r = idx >> 5, sg = (idx & 31) * 8;
            *(uint4*)&Ks[r][sg] = *(const uint4*)(KgB + (size_t)(kt + r) * ld + sg);
            *(uint4*)&Vs[r][sg] = *(const uint4*)(VgB + (size_t)(kt + r) * ld + sg);
        }
        __syncthreads();

        float sc[4] = {0.f, 0.f, 0.f, 0.f};
#pragma unroll
        for (int s = 0; s < 16; s++) {
            uint32_t ku[2];
            ldsm_x2(kaddr + s * 32, ku);
            mma_f16(sc, qf[s], ku);
        }
        {
            int rw = wm * 16 + gid, c = wn * 8 + 2 * tig;
            float2 v;
            v.x = sc[0] * scale; v.y = sc[1] * scale;
            *(float2*)&SP[rw][c] = v;
            v.x = sc[2] * scale; v.y = sc[3] * scale;
            *(float2*)&SP[rw + 8][c] = v;
        }
        __syncthreads();

        {
            int row = tid >> 3, c0 = (tid & 7) * 4;
            float4 sv = *(const float4*)&SP[row][c0];
            float mx = fmaxf(fmaxf(sv.x, sv.y), fmaxf(sv.z, sv.w));
            mx = fmaxf(mx, __shfl_xor_sync(0xffffffffu, mx, 1));
            mx = fmaxf(mx, __shfl_xor_sync(0xffffffffu, mx, 2));
            mx = fmaxf(mx, __shfl_xor_sync(0xffffffffu, mx, 4));
            float mold = Mst[row];
            float mnew = fmaxf(mold, mx);
            float p0 = __expf(sv.x - mnew), p1 = __expf(sv.y - mnew);
            float p2 = __expf(sv.z - mnew), p3 = __expf(sv.w - mnew);
            float ps = p0 + p1 + p2 + p3;
            ps += __shfl_xor_sync(0xffffffffu, ps, 1);
            ps += __shfl_xor_sync(0xffffffffu, ps, 2);
            ps += __shfl_xor_sync(0xffffffffu, ps, 4);
            if ((tid & 7) == 0) {
                float al = __expf(mold - mnew);
                Mst[row] = mnew; Lst[row] = Lst[row] * al + ps; Alp[row] = al;
            }
            uint2 pu; pu.x = packh2(p0, p1); pu.y = packh2(p2, p3);
            *(uint2*)&SPh[row][c0] = pu;
        }
        __syncthreads();

        float al0 = Alp[wm * 16 + gid], al1 = Alp[wm * 16 + gid + 8];
#pragma unroll
        for (int nf = 0; nf < 8; nf++) {
            oacc[nf][0] *= al0; oacc[nf][1] *= al0;
            oacc[nf][2] *= al1; oacc[nf][3] *= al1;
        }

#pragma unroll
        for (int s2 = 0; s2 < 2; s2++) {
            uint32_t pa[4];
            ldsm_x4(paddr + s2 * 32, pa);
#pragma unroll
            for (int nfp = 0; nfp < 4; nfp++) {
                uint32_t vu[4];
                ldsm_x4_t(vaddr + s2 * 8448 + nfp * 32, vu);
                mma_f16(oacc[nfp * 2],     pa, vu + 0);
                mma_f16(oacc[nfp * 2 + 1], pa, vu + 2);
            }
        }
    }

    float inv0 = 1.f / Lst[wm * 16 + gid], inv1 = 1.f / Lst[wm * 16 + gid + 8];
    __half* Og = Ob + (size_t)(b * S + q0 + wm * 16) * H + h * BD;
#pragma unroll
    for (int nf = 0; nf < 8; nf++) {
        int c = wn * 64 + nf * 8 + 2 * tig;
        *(uint32_t*)(Og + (size_t)gid * H + c) =
            packh2(oacc[nf][0] * inv0, oacc[nf][1] * inv0);
        *(uint32_t*)(Og + (size_t)(gid + 8) * H + c) =
            packh2(oacc[nf][2] * inv1, oacc[nf][3] * inv1);
    }
}

// ---------------- launch ----------------
extern "C" void kernel_launch(void* const* d_in, const int* in_sizes, int n_in,
                              void* d_out, int out_size)
{
    (void)in_sizes; (void)n_in; (void)out_size;
    const float* hs      = (const float*)d_in[0];
    const int*   mask    = (const int*)  d_in[1];
    const float* cvec    = (const float*)d_in[2];
    const float* Wq      = (const float*)d_in[3];
    const float* bq      = (const float*)d_in[4];
    const float* Wk      = (const float*)d_in[5];
    const float* bk      = (const float*)d_in[6];
    const float* Wv      = (const float*)d_in[7];
    const float* bv      = (const float*)d_in[8];
    const float* Wg      = (const float*)d_in[9];
    const float* bg      = (const float*)d_in[10];
    const float* Wa      = (const float*)d_in[11];
    const float* ba      = (const float*)d_in[12];
    const float* ca_in_w = (const float*)d_in[13];
    const float* ca_in_b = (const float*)d_in[14];
    const float* ca_ow   = (const float*)d_in[15];
    const float* ca_ob   = (const float*)d_in[16];
    const float* ma_in_w = (const float*)d_in[17];
    const float* ma_in_b = (const float*)d_in[18];
    const float* ma_ow   = (const float*)d_in[19];
    const float* ma_ob   = (const float*)d_in[20];
    const float* Wo      = (const float*)d_in[21];
    const float* bo      = (const float*)d_in[22];

    __half *Q, *K, *V, *QKV3, *T1, *HSh, *WH;
    float *MOD, *CTX;
    cudaGetSymbolAddress((void**)&Q, g_Q);
    cudaGetSymbolAddress((void**)&K, g_K);
    cudaGetSymbolAddress((void**)&V, g_V);
    cudaGetSymbolAddress((void**)&MOD, g_MOD);
    cudaGetSymbolAddress((void**)&CTX, g_CTX);
    cudaGetSymbolAddress((void**)&QKV3, g_QKV3);
    cudaGetSymbolAddress((void**)&T1, g_T1);
    cudaGetSymbolAddress((void**)&HSh, g_HSh);
    cudaGetSymbolAddress((void**)&WH, g_WH);

    // half-weight pool offsets
    __half* WqH = WH + 0 * (size_t)MHH;
    __half* WkH = WH + 1 * (size_t)MHH;
    __half* WvH = WH + 2 * (size_t)MHH;
    __half* caInH = WH + 3 * (size_t)MHH;    // 3 MHH
    __half* caOwH = WH + 6 * (size_t)MHH;
    __half* maInH = WH + 7 * (size_t)MHH;    // 3 MHH
    __half* maOwH = WH + 10 * (size_t)MHH;
    __half* WoH = WH + 11 * (size_t)MHH;

    // single fused convert launch (block = 2048 elems; all sizes divisible)
    CvtJobs cj;
    cj.src[0] = hs;      cj.dst[0] = HSh;   // 2048 blocks
    cj.src[1] = Wq;      cj.dst[1] = WqH;   // 512
    cj.src[2] = Wk;      cj.dst[2] = WkH;   // 512
    cj.src[3] = Wv;      cj.dst[3] = WvH;   // 512
    cj.src[4] = ca_in_w; cj.dst[4] = caInH; // 1536
    cj.src[5] = ca_ow;   cj.dst[5] = caOwH; // 512
    cj.src[6] = ma_in_w; cj.dst[6] = maInH; // 1536
    cj.src[7] = ma_ow;   cj.dst[7] = maOwH; // 512
    cj.src[8] = Wo;      cj.dst[8] = WoH;   // 512
    cj.start[0] = 0;    cj.start[1] = 2048; cj.start[2] = 2560; cj.start[3] = 3072;
    cj.start[4] = 3584; cj.start[5] = 5120; cj.start[6] = 5632; cj.start[7] = 7168;
    cj.start[8] = 7680; cj.start[9] = 8192;
    cvt_all<<<8192, 256>>>(cj);

    dim3 gN1(H / 128, MS / 128);
    dim3 gN3(3 * H / 128, MS / 128);

    // main attention path
    gemm_tc<__half, __half, false><<<gN1, 256>>>(HSh, WqH, bq, Q, MS, H, H, nullptr, 0.f, 0.f);
    gemm_tc<__half, __half, false><<<gN1, 256>>>(HSh, WkH, bk, K, MS, H, H, nullptr, 0.f, 0.f);
    gemm_tc<__half, __half, false><<<gN1, 256>>>(HSh, WvH, bv, V, MS, H, H, nullptr, 0.f, 0.f);
    gatemod2<<<MS / 16, 256>>>(hs, Wg, bg, cvec, Wa, ba, MOD);
    attn_main_f16<<<dim3(S / 128, NH, B), 256>>>(Q, K, V, MOD, mask, CTX);

    // causal branch (blend fused into out-proj epilogue)
    gemm_tc<__half, __half, false><<<gN3, 256>>>(HSh, caInH, ca_in_b, QKV3, MS, 3 * H, H, nullptr, 0.f, 0.f);
    attn_big_f16<<<dim3(S / 32, BH, B), 256>>>(QKV3, QKV3 + H, QKV3 + 2 * H, 3 * H, T1, 0.0625f);
    gemm_tc<__half, float, true><<<gN1, 256>>>(T1, caOwH, ca_ob, CTX, MS, H, H, CTX, 0.3f, 0.7f);

    // metacognitive branch (blend fused)
    gemm_tc<float, __half, false><<<gN3, 256>>>(CTX, maInH, ma_in_b, QKV3, MS, 3 * H, H, nullptr, 0.f, 0.f);
    attn_big_f16<<<dim3(S / 32, BH, B), 256>>>(QKV3, QKV3 + H, QKV3 + 2 * H, 3 * H, T1, 0.0625f);
    gemm_tc<__half, float, true><<<gN1, 256>>>(T1, maOwH, ma_ob, CTX, MS, H, H, CTX, 0.85f, 0.15f);

    // output projection
    gemm_tc<float, float, false><<<gN1, 256>>>(CTX, WoH, bo, (float*)d_out, MS, H, H, nullptr, 0.f, 0.f);
}

// round 11
// speedup vs baseline: 1.4746x; 1.4746x over previous
#include <cuda_runtime.h>
#include <cuda_fp16.h>
#include <stdint.h>
#include <math.h>

#define B 2
#define S 2048
#define H 1024
#define NH 16
#define HD 64
#define BH 4
#define BD 256
#define MS (B*S)   /* 4096 rows */
#define MHH (H*H)  /* 1048576 */

// ---------------- scratch (static device globals; no allocations) ----------------
__device__ __half g_Q[MS * H];
__device__ __half g_K[MS * H];
__device__ __half g_V[MS * H];
__device__ float  g_MOD[MS * NH];
__device__ float  g_CTX[MS * H];
__device__ __half g_QKV3[MS * 3 * H];
__device__ __half g_T1[MS * H];
__device__ __half g_HSh[MS * H];       // hs in half
__device__ __half g_WH[12 * MHH];      // all weights in half

// ---------------- helpers ----------------
__device__ __forceinline__ uint32_t cvta_s(const void* p) {
    return (uint32_t)__cvta_generic_to_shared(p);
}
__device__ __forceinline__ uint32_t packh2(float a, float b) {
    __half2 h = __floats2half2_rn(a, b);
    return *reinterpret_cast<uint32_t*>(&h);
}
__device__ __forceinline__ void ldsm_x4(uint32_t addr, uint32_t* r) {
    asm volatile("ldmatrix.sync.aligned.m8n8.x4.shared.b16 {%0,%1,%2,%3}, [%4];"
        : "=r"(r[0]), "=r"(r[1]), "=r"(r[2]), "=r"(r[3]) : "r"(addr));
}
__device__ __forceinline__ void ldsm_x4_t(uint32_t addr, uint32_t* r) {
    asm volatile("ldmatrix.sync.aligned.m8n8.x4.trans.shared.b16 {%0,%1,%2,%3}, [%4];"
        : "=r"(r[0]), "=r"(r[1]), "=r"(r[2]), "=r"(r[3]) : "r"(addr));
}
__device__ __forceinline__ void ldsm_x2(uint32_t addr, uint32_t* r) {
    asm volatile("ldmatrix.sync.aligned.m8n8.x2.shared.b16 {%0,%1}, [%2];"
        : "=r"(r[0]), "=r"(r[1]) : "r"(addr));
}
__device__ __forceinline__ void mma_f16(float* d, const uint32_t* a, const uint32_t* b) {
    asm volatile(
        "mma.sync.aligned.m16n8k16.row.col.f32.f16.f16.f32 "
        "{%0,%1,%2,%3}, {%4,%5,%6,%7}, {%8,%9}, {%0,%1,%2,%3};"
        : "+f"(d[0]), "+f"(d[1]), "+f"(d[2]), "+f"(d[3])
        : "r"(a[0]), "r"(a[1]), "r"(a[2]), "r"(a[3]), "r"(b[0]), "r"(b[1]));
}

// ---------------- fp32 -> fp16 convert (vectorized, 8 elems/thread) ----------------
__global__ __launch_bounds__(256) void cvt_h(const float* __restrict__ src,
                                             __half* __restrict__ dst, int n)
{
    int i = (blockIdx.x * 256 + threadIdx.x) * 8;
    if (i < n) {
        float4 a = *(const float4*)(src + i);
        float4 b = *(const float4*)(src + i + 4);
        uint4 o;
        o.x = packh2(a.x, a.y); o.y = packh2(a.z, a.w);
        o.z = packh2(b.x, b.y); o.w = packh2(b.z, b.w);
        *(uint4*)(dst + i) = o;
    }
}

// ---------------- FP16 tensor-core GEMM (double-buffered smem) ----------------
// block 128x128x32, 8 warps 2x4, warp tile 64x32, mma m16n8k16, ldmatrix frags
#define A_BUF_B 10240   /* 128*40*2 bytes */
#define B_BUF_B 8704    /* 32*136*2 bytes */

template<typename TA, typename TO, bool BLEND>
__global__ __launch_bounds__(256) void gemm_tc(
    const TA* __restrict__ A, const __half* __restrict__ W,
    const float* __restrict__ bias, TO* __restrict__ C,
    int M, int N, int K,
    const float* __restrict__ bld, float wa, float wb)
{
    __shared__ __half As[2][128][40];    // row stride 80B
    __shared__ __half Bs[2][32][136];    // row stride 272B

    int tid = threadIdx.x, warp = tid >> 5, lane = tid & 31;
    int wm = (warp >> 2) * 64, wn = (warp & 3) * 32;
    int m0 = blockIdx.y * 128, n0 = blockIdx.x * 128;
    int gid = lane >> 2, tig = lane & 3;

    float acc[4][4][4];
#pragma unroll
    for (int mt = 0; mt < 4; mt++)
#pragma unroll
        for (int nt = 0; nt < 4; nt++)
#pragma unroll
            for (int r = 0; r < 4; r++) acc[mt][nt][r] = 0.f;

    int aRow[4], aCol[4], bRow[4], bCol[4];
#pragma unroll
    for (int i = 0; i < 4; i++) {
        int fi = tid + 256 * i;
        aRow[i] = fi >> 3;  aCol[i] = (fi & 7) * 4;
        bRow[i] = fi >> 5;  bCol[i] = (fi & 31) * 4;
    }

    int lr = ((lane >> 3) & 1) * 8 + (lane & 7);
    int lc = (lane >> 4) * 8;
    uint32_t a_addr[4], b_addr[2];
#pragma unroll
    for (int mt = 0; mt < 4; mt++)
        a_addr[mt] = cvta_s(&As[0][wm + mt * 16 + lr][lc]);
#pragma unroll
    for (int ntp = 0; ntp < 2; ntp++)
        b_addr[ntp] = cvta_s(&Bs[0][lr][wn + ntp * 16 + lc]);

    auto loadTile = [&](int kb, uint2* aPk, uint2* bPk) {
#pragma unroll
        for (int i = 0; i < 4; i++) {
            if constexpr (sizeof(TA) == 4) {
                float4 av = *(const float4*)((const float*)A + (size_t)(m0 + aRow[i]) * K + kb + aCol[i]);
                aPk[i].x = packh2(av.x, av.y); aPk[i].y = packh2(av.z, av.w);
            } else {
                aPk[i] = *(const uint2*)((const __half*)A + (size_t)(m0 + aRow[i]) * K + kb + aCol[i]);
            }
            bPk[i] = *(const uint2*)(W + (size_t)(kb + bRow[i]) * N + n0 + bCol[i]);
        }
    };
    auto storeTile = [&](int buf, const uint2* aPk, const uint2* bPk) {
#pragma unroll
        for (int i = 0; i < 4; i++) {
            *(uint2*)&As[buf][aRow[i]][aCol[i]] = aPk[i];
            *(uint2*)&Bs[buf][bRow[i]][bCol[i]] = bPk[i];
        }
    };

    int ntiles = K / 32;
    uint2 aPk[4], bPk[4];
    loadTile(0, aPk, bPk);
    storeTile(0, aPk, bPk);
    __syncthreads();
    if (ntiles > 1) loadTile(32, aPk, bPk);

    for (int kt = 0; kt < ntiles; kt++) {
        int buf = kt & 1;
        uint32_t aoff = (uint32_t)buf * A_BUF_B;
        uint32_t boff = (uint32_t)buf * B_BUF_B;
#pragma unroll
        for (int q = 0; q < 2; q++) {
            int kq = q * 16;
            uint32_t af[4][4], bu0[4], bu1[4];
#pragma unroll
            for (int mt = 0; mt < 4; mt++) ldsm_x4(a_addr[mt] + aoff + kq * 2, af[mt]);
            ldsm_x4_t(b_addr[0] + boff + kq * 272, bu0);
            ldsm_x4_t(b_addr[1] + boff + kq * 272, bu1);
#pragma unroll
            for (int mt = 0; mt < 4; mt++) {
                mma_f16(acc[mt][0], af[mt], bu0 + 0);
                mma_f16(acc[mt][1], af[mt], bu0 + 2);
                mma_f16(acc[mt][2], af[mt], bu1 + 0);
                mma_f16(acc[mt][3], af[mt], bu1 + 2);
            }
        }
        if (kt + 1 < ntiles) {
            storeTile(buf ^ 1, aPk, bPk);
            __syncthreads();
            if (kt + 2 < ntiles) loadTile((kt + 2) * 32, aPk, bPk);
        }
    }

#pragma unroll
    for (int mt = 0; mt < 4; mt++) {
        int r0 = m0 + wm + mt * 16 + gid;
#pragma unroll
        for (int nt = 0; nt < 4; nt++) {
            int c = n0 + wn + nt * 8 + tig * 2;
            float b0v = bias[c], b1v = bias[c + 1];
            float e00 = acc[mt][nt][0] + b0v, e01 = acc[mt][nt][1] + b1v;
            float e10 = acc[mt][nt][2] + b0v, e11 = acc[mt][nt][3] + b1v;
            if constexpr (BLEND) {
                float2 x0 = *(const float2*)(bld + (size_t)r0 * N + c);
                float2 x1 = *(const float2*)(bld + (size_t)(r0 + 8) * N + c);
                e00 = x0.x * wa + e00 * wb; e01 = x0.y * wa + e01 * wb;
                e10 = x1.x * wa + e10 * wb; e11 = x1.y * wa + e11 * wb;
            }
            if constexpr (sizeof(TO) == 2) {
                *(uint32_t*)((__half*)C + (size_t)r0 * N + c) = packh2(e00, e01);
                *(uint32_t*)((__half*)C + (size_t)(r0 + 8) * N + c) = packh2(e10, e11);
            } else {
                float2 v0, v1;
                v0.x = e00; v0.y = e01; v1.x = e10; v1.y = e11;
                *(float2*)((float*)C + (size_t)r0 * N + c) = v0;
                *(float2*)((float*)C + (size_t)(r0 + 8) * N + c) = v1;
            }
        }
    }
}

// ---------------- modulation (smem-tiled): sigmoid(hs@Wg + bg + cvec@Wa + ba) ----------------
__global__ __launch_bounds__(256) void gatemod2(
    const float* __restrict__ hs, const float* __restrict__ Wg,
    const float* __restrict__ bg, const float* __restrict__ cvec,
    const float* __restrict__ Wa, const float* __restrict__ ba,
    float* __restrict__ MODo)
{
    __shared__ float Wgs[64][16];
    __shared__ float hss[16][68];
    __shared__ float awS[16];

    int tid = threadIdx.x;
    int m0 = blockIdx.x * 16;
    int r = tid >> 4, n = tid & 15;

    if (tid < 16) {
        float aw = ba[tid] + bg[tid];
#pragma unroll
        for (int k = 0; k < 16; k++) aw += cvec[k] * Wa[k * 16 + tid];
        awS[tid] = aw;
    }

    float acc = 0.f;
    for (int kt = 0; kt < H; kt += 64) {
        __syncthreads();
        *(float4*)&((float*)Wgs)[tid * 4] = *(const float4*)&Wg[kt * 16 + tid * 4];
        int r2 = tid >> 4, k2 = (tid & 15) * 4;
        *(float4*)&hss[r2][k2] = *(const float4*)&hs[(size_t)(m0 + r2) * H + kt + k2];
        __syncthreads();
#pragma unroll
        for (int k = 0; k < 64; k++) acc += hss[r][k] * Wgs[k][n];
    }
    float x = acc + awS[n];
    MODo[(size_t)(m0 + r) * NH + n] = 1.f / (1.f + __expf(-x));
}

// ---------------- main attention (fp16 TC): 16 heads, hd=64 ----------------
__global__ __launch_bounds__(256) void attn_main_f16(
    const __half* __restrict__ Qb, const __half* __restrict__ Kb,
    const __half* __restrict__ Vb, const float* __restrict__ MODb,
    const int* __restrict__ maskb, float* __restrict__ Ob)
{
    __shared__ __half Ks[32][72];   // [key][d], 144B stride
    __shared__ __half Vs[32][72];
    __shared__ float Madd[32];

    int tid = threadIdx.x, lane = tid & 31, warp = tid >> 5;
    int gid = lane >> 2, tig = lane & 3;
    int q0 = blockIdx.x * 128, h = blockIdx.y, b = blockIdx.z;
    int qw = q0 + warp * 16;

    uint32_t qf[4][4];
    const __half* Qg = Qb + (size_t)(b * S + qw) * H + h * HD;
#pragma unroll
    for (int s = 0; s < 4; s++) {
        int c0 = s * 16 + 2 * tig;
        qf[s][0] = *(const uint32_t*)(Qg + (size_t)gid * H + c0);
        qf[s][1] = *(const uint32_t*)(Qg + (size_t)(gid + 8) * H + c0);
        qf[s][2] = *(const uint32_t*)(Qg + (size_t)gid * H + c0 + 8);
        qf[s][3] = *(const uint32_t*)(Qg + (size_t)(gid + 8) * H + c0 + 8);
    }
    float mod0 = MODb[(size_t)(b * S + qw + gid) * NH + h] * 0.125f;
    float mod1 = MODb[(size_t)(b * S + qw + gid + 8) * NH + h] * 0.125f;

    uint32_t kaddr[2], vaddr[4];
#pragma unroll
    for (int ntp = 0; ntp < 2; ntp++)
        kaddr[ntp] = cvta_s(&Ks[(ntp * 2 + (lane >> 4)) * 8 + (lane & 7)][((lane >> 3) & 1) * 8]);
#pragma unroll
    for (int nfp = 0; nfp < 4; nfp++)
        vaddr[nfp] = cvta_s(&Vs[((lane >> 3) & 1) * 8 + (lane & 7)][(nfp * 2 + (lane >> 4)) * 8]);

    int cr = tid >> 3, cs = (tid & 7) * 8;
    const __half* KgB = Kb + (size_t)(b * S) * H + h * HD;
    const __half* VgB = Vb + (size_t)(b * S) * H + h * HD;

    float m0v = -1e30f, m1v = -1e30f, l0 = 0.f, l1 = 0.f;
    float oacc[8][4];
#pragma unroll
    for (int nf = 0; nf < 8; nf++)
#pragma unroll
        for (int r = 0; r < 4; r++) oacc[nf][r] = 0.f;

    for (int kt = 0; kt < S; kt += 32) {
        __syncthreads();
        *(uint4*)&Ks[cr][cs] = *(const uint4*)(KgB + (size_t)(kt + cr) * H + cs);
        *(uint4*)&Vs[cr][cs] = *(const uint4*)(VgB + (size_t)(kt + cr) * H + cs);
        if (tid < 32) Madd[tid] = maskb[b * S + kt + tid] ? 0.f : -1e30f;
        __syncthreads();

        float sc[4][4];
#pragma unroll
        for (int nf = 0; nf < 4; nf++)
#pragma unroll
            for (int r = 0; r < 4; r++) sc[nf][r] = 0.f;
#pragma unroll
        for (int s = 0; s < 4; s++) {
            uint32_t ku0[4], ku1[4];
            ldsm_x4(kaddr[0] + s * 32, ku0);
            ldsm_x4(kaddr[1] + s * 32, ku1);
            mma_f16(sc[0], qf[s], ku0 + 0);
            mma_f16(sc[1], qf[s], ku0 + 2);
            mma_f16(sc[2], qf[s], ku1 + 0);
            mma_f16(sc[3], qf[s], ku1 + 2);
        }

        float mx0 = -1e30f, mx1 = -1e30f;
#pragma unroll
        for (int nf = 0; nf < 4; nf++) {
            float ma = Madd[nf * 8 + 2 * tig], mb2 = Madd[nf * 8 + 2 * tig + 1];
            sc[nf][0] = sc[nf][0] * mod0 + ma;
            sc[nf][1] = sc[nf][1] * mod0 + mb2;
            sc[nf][2] = sc[nf][2] * mod1 + ma;
            sc[nf][3] = sc[nf][3] * mod1 + mb2;
            mx0 = fmaxf(mx0, fmaxf(sc[nf][0], sc[nf][1]));
            mx1 = fmaxf(mx1, fmaxf(sc[nf][2], sc[nf][3]));
        }
        mx0 = fmaxf(mx0, __shfl_xor_sync(0xffffffffu, mx0, 1));
        mx0 = fmaxf(mx0, __shfl_xor_sync(0xffffffffu, mx0, 2));
        mx1 = fmaxf(mx1, __shfl_xor_sync(0xffffffffu, mx1, 1));
        mx1 = fmaxf(mx1, __shfl_xor_sync(0xffffffffu, mx1, 2));
        float mn0 = fmaxf(m0v, mx0), mn1 = fmaxf(m1v, mx1);
        float al0 = __expf(m0v - mn0), al1 = __expf(m1v - mn1);
        float ps0 = 0.f, ps1 = 0.f;
        uint32_t pva[2][4];
#pragma unroll
        for (int nf = 0; nf < 4; nf++) {
            float p00 = __expf(sc[nf][0] - mn0), p01 = __expf(sc[nf][1] - mn0);
            float p10 = __expf(sc[nf][2] - mn1), p11 = __expf(sc[nf][3] - mn1);
            ps0 += p00 + p01; ps1 += p10 + p11;
            int s2 = nf >> 1, hi = (nf & 1) * 2;
            pva[s2][hi]     = packh2(p00, p01);
            pva[s2][hi + 1] = packh2(p10, p11);
        }
        ps0 += __shfl_xor_sync(0xffffffffu, ps0, 1);
        ps0 += __shfl_xor_sync(0xffffffffu, ps0, 2);
        ps1 += __shfl_xor_sync(0xffffffffu, ps1, 1);
        ps1 += __shfl_xor_sync(0xffffffffu, ps1, 2);
        l0 = l0 * al0 + ps0; l1 = l1 * al1 + ps1;
        m0v = mn0; m1v = mn1;
#pragma unroll
        for (int nf = 0; nf < 8; nf++) {
            oacc[nf][0] *= al0; oacc[nf][1] *= al0;
            oacc[nf][2] *= al1; oacc[nf][3] *= al1;
        }

#pragma unroll
        for (int s2 = 0; s2 < 2; s2++) {
#pragma unroll
            for (int nfp = 0; nfp < 4; nfp++) {
                uint32_t vu[4];
                ldsm_x4_t(vaddr[nfp] + s2 * 16 * 144, vu);
                mma_f16(oacc[nfp * 2],     pva[s2], vu + 0);
                mma_f16(oacc[nfp * 2 + 1], pva[s2], vu + 2);
            }
        }
    }

    float inv0 = 1.f / l0, inv1 = 1.f / l1;
    float* Og = Ob + (size_t)(b * S + qw) * H + h * HD;
#pragma unroll
    for (int nf = 0; nf < 8; nf++) {
        int c = nf * 8 + 2 * tig;
        float2 v0, v1;
        v0.x = oacc[nf][0] * inv0; v0.y = oacc[nf][1] * inv0;
        v1.x = oacc[nf][2] * inv1; v1.y = oacc[nf][3] * inv1;
        *(float2*)(Og + (size_t)gid * H + c) = v0;
        *(float2*)(Og + (size_t)(gid + 8) * H + c) = v1;
    }
}

// ---------------- big-head attention (fp16 TC): 4 heads, hd=256 ----------------
__global__ __launch_bounds__(256) void attn_big_f16(
    const __half* __restrict__ Qb, const __half* __restrict__ Kb,
    const __half* __restrict__ Vb, int ld, __half* __restrict__ Ob, float scale)
{
    __shared__ __half Ks[32][264];   // [key][d], 528B stride
    __shared__ __half Vs[32][264];
    __shared__ float SP[32][36];
    __shared__ __half SPh[32][40];
    __shared__ float Mst[32], Lst[32], Alp[32];

    int tid = threadIdx.x, lane = tid & 31, warp = tid >> 5;
    int gid = lane >> 2, tig = lane & 3;
    int wm = warp >> 2, wn = warp & 3;
    int q0 = blockIdx.x * 32, h = blockIdx.y, b = blockIdx.z;

    uint32_t qf[16][4];
    const __half* Qg = Qb + (size_t)(b * S + q0 + wm * 16) * ld + h * BD;
#pragma unroll
    for (int s = 0; s < 16; s++) {
        int c0 = s * 16 + 2 * tig;
        qf[s][0] = *(const uint32_t*)(Qg + (size_t)gid * ld + c0);
        qf[s][1] = *(const uint32_t*)(Qg + (size_t)(gid + 8) * ld + c0);
        qf[s][2] = *(const uint32_t*)(Qg + (size_t)gid * ld + c0 + 8);
        qf[s][3] = *(const uint32_t*)(Qg + (size_t)(gid + 8) * ld + c0 + 8);
    }
    if (tid < 32) { Mst[tid] = -1e30f; Lst[tid] = 0.f; }

    uint32_t kaddr = cvta_s(&Ks[wn * 8 + (lane & 7)][((lane >> 3) & 1) * 8]);
    uint32_t paddr = cvta_s(&SPh[wm * 16 + ((lane >> 3) & 1) * 8 + (lane & 7)][(lane >> 4) * 8]);
    uint32_t vaddr = cvta_s(&Vs[((lane >> 3) & 1) * 8 + (lane & 7)][wn * 64 + (lane >> 4) * 8]);

    const __half* KgB = Kb + (size_t)(b * S) * ld + h * BD;
    const __half* VgB = Vb + (size_t)(b * S) * ld + h * BD;

    float oacc[8][4];
#pragma unroll
    for (int nf = 0; nf < 8; nf++)
#pragma unroll
        for (int r = 0; r < 4; r++) oacc[nf][r] = 0.f;

    for (int kt = 0; kt < S; kt += 32) {
        __syncthreads();
#pragma unroll
        for (int it = 0; it < 4; it++) {
            int idx = tid + it * 256;
            int r = idx >> 5, sg = (idx & 31) * 8;
            *(uint4*)&Ks[r][sg] = *(const uint4*)(KgB + (size_t)(kt + r) * ld + sg);
            *(uint4*)&Vs[r][sg] = *(const uint4*)(VgB + (size_t)(kt + r) * ld + sg);
        }
        __syncthreads();

        float sc[4] = {0.f, 0.f, 0.f, 0.f};
#pragma unroll
        for (int s = 0; s < 16; s++) {
            uint32_t ku[2];
            ldsm_x2(kaddr + s * 32, ku);
            mma_f16(sc, qf[s], ku);
        }
        {
            int rw = wm * 16 + gid, c = wn * 8 + 2 * tig;
            float2 v;
            v.x = sc[0] * scale; v.y = sc[1] * scale;
            *(float2*)&SP[rw][c] = v;
            v.x = sc[2] * scale; v.y = sc[3] * scale;
            *(float2*)&SP[rw + 8][c] = v;
        }
        __syncthreads();

        {
            int row = tid >> 3, c0 = (tid & 7) * 4;
            float4 sv = *(const float4*)&SP[row][c0];
            float mx = fmaxf(fmaxf(sv.x, sv.y), fmaxf(sv.z, sv.w));
            mx = fmaxf(mx, __shfl_xor_sync(0xffffffffu, mx, 1));
            mx = fmaxf(mx, __shfl_xor_sync(0xffffffffu, mx, 2));
            mx = fmaxf(mx, __shfl_xor_sync(0xffffffffu, mx, 4));
            float mold = Mst[row];
            float mnew = fmaxf(mold, mx);
            float p0 = __expf(sv.x - mnew), p1 = __expf(sv.y - mnew);
            float p2 = __expf(sv.z - mnew), p3 = __expf(sv.w - mnew);
            float ps = p0 + p1 + p2 + p3;
            ps += __shfl_xor_sync(0xffffffffu, ps, 1);
            ps += __shfl_xor_sync(0xffffffffu, ps, 2);
            ps += __shfl_xor_sync(0xffffffffu, ps, 4);
            if ((tid & 7) == 0) {
                float al = __expf(mold - mnew);
                Mst[row] = mnew; Lst[row] = Lst[row] * al + ps; Alp[row] = al;
            }
            uint2 pu; pu.x = packh2(p0, p1); pu.y = packh2(p2, p3);
            *(uint2*)&SPh[row][c0] = pu;
        }
        __syncthreads();

        float al0 = Alp[wm * 16 + gid], al1 = Alp[wm * 16 + gid + 8];
#pragma unroll
        for (int nf = 0; nf < 8; nf++) {
            oacc[nf][0] *= al0; oacc[nf][1] *= al0;
            oacc[nf][2] *= al1; oacc[nf][3] *= al1;
        }

#pragma unroll
        for (int s2 = 0; s2 < 2; s2++) {
            uint32_t pa[4];
            ldsm_x4(paddr + s2 * 32, pa);
#pragma unroll
            for (int nfp = 0; nfp < 4; nfp++) {
                uint32_t vu[4];
                ldsm_x4_t(vaddr + s2 * 8448 + nfp * 32, vu);
                mma_f16(oacc[nfp * 2],     pa, vu + 0);
                mma_f16(oacc[nfp * 2 + 1], pa, vu + 2);
            }
        }
    }

    float inv0 = 1.f / Lst[wm * 16 + gid], inv1 = 1.f / Lst[wm * 16 + gid + 8];
    __half* Og = Ob + (size_t)(b * S + q0 + wm * 16) * H + h * BD;
#pragma unroll
    for (int nf = 0; nf < 8; nf++) {
        int c = wn * 64 + nf * 8 + 2 * tig;
        *(uint32_t*)(Og + (size_t)gid * H + c) =
            packh2(oacc[nf][0] * inv0, oacc[nf][1] * inv0);
        *(uint32_t*)(Og + (size_t)(gid + 8) * H + c) =
            packh2(oacc[nf][2] * inv1, oacc[nf][3] * inv1);
    }
}

// ---------------- launch ----------------
extern "C" void kernel_launch(void* const* d_in, const int* in_sizes, int n_in,
                              void* d_out, int out_size)
{
    (void)in_sizes; (void)n_in; (void)out_size;
    const float* hs      = (const float*)d_in[0];
    const int*   mask    = (const int*)  d_in[1];
    const float* cvec    = (const float*)d_in[2];
    const float* Wq      = (const float*)d_in[3];
    const float* bq      = (const float*)d_in[4];
    const float* Wk      = (const float*)d_in[5];
    const float* bk      = (const float*)d_in[6];
    const float* Wv      = (const float*)d_in[7];
    const float* bv      = (const float*)d_in[8];
    const float* Wg      = (const float*)d_in[9];
    const float* bg      = (const float*)d_in[10];
    const float* Wa      = (const float*)d_in[11];
    const float* ba      = (const float*)d_in[12];
    const float* ca_in_w = (const float*)d_in[13];
    const float* ca_in_b = (const float*)d_in[14];
    const float* ca_ow   = (const float*)d_in[15];
    const float* ca_ob   = (const float*)d_in[16];
    const float* ma_in_w = (const float*)d_in[17];
    const float* ma_in_b = (const float*)d_in[18];
    const float* ma_ow   = (const float*)d_in[19];
    const float* ma_ob   = (const float*)d_in[20];
    const float* Wo      = (const float*)d_in[21];
    const float* bo      = (const float*)d_in[22];

    __half *Q, *K, *V, *QKV3, *T1, *HSh, *WH;
    float *MOD, *CTX;
    cudaGetSymbolAddress((void**)&Q, g_Q);
    cudaGetSymbolAddress((void**)&K, g_K);
    cudaGetSymbolAddress((void**)&V, g_V);
    cudaGetSymbolAddress((void**)&MOD, g_MOD);
    cudaGetSymbolAddress((void**)&CTX, g_CTX);
    cudaGetSymbolAddress((void**)&QKV3, g_QKV3);
    cudaGetSymbolAddress((void**)&T1, g_T1);
    cudaGetSymbolAddress((void**)&HSh, g_HSh);
    cudaGetSymbolAddress((void**)&WH, g_WH);

    // half-weight pool offsets
    __half* WqH = WH + 0 * (size_t)MHH;
    __half* WkH = WH + 1 * (size_t)MHH;
    __half* WvH = WH + 2 * (size_t)MHH;
    __half* caInH = WH + 3 * (size_t)MHH;    // 3 MHH
    __half* caOwH = WH + 6 * (size_t)MHH;
    __half* maInH = WH + 7 * (size_t)MHH;    // 3 MHH
    __half* maOwH = WH + 10 * (size_t)MHH;
    __half* WoH = WH + 11 * (size_t)MHH;

    // converts (8 elems/thread, 2048 elems/block)
    cvt_h<<<MS * H / 2048, 256>>>(hs, HSh, MS * H);
    cvt_h<<<MHH / 2048, 256>>>(Wq, WqH, MHH);
    cvt_h<<<MHH / 2048, 256>>>(Wk, WkH, MHH);
    cvt_h<<<MHH / 2048, 256>>>(Wv, WvH, MHH);
    cvt_h<<<3 * MHH / 2048, 256>>>(ca_in_w, caInH, 3 * MHH);
    cvt_h<<<MHH / 2048, 256>>>(ca_ow, caOwH, MHH);
    cvt_h<<<3 * MHH / 2048, 256>>>(ma_in_w, maInH, 3 * MHH);
    cvt_h<<<MHH / 2048, 256>>>(ma_ow, maOwH, MHH);
    cvt_h<<<MHH / 2048, 256>>>(Wo, WoH, MHH);

    dim3 gN1(H / 128, MS / 128);
    dim3 gN3(3 * H / 128, MS / 128);

    // main attention path
    gemm_tc<__half, __half, false><<<gN1, 256>>>(HSh, WqH, bq, Q, MS, H, H, nullptr, 0.f, 0.f);
    gemm_tc<__half, __half, false><<<gN1, 256>>>(HSh, WkH, bk, K, MS, H, H, nullptr, 0.f, 0.f);
    gemm_tc<__half, __half, false><<<gN1, 256>>>(HSh, WvH, bv, V, MS, H, H, nullptr, 0.f, 0.f);
    gatemod2<<<MS / 16, 256>>>(hs, Wg, bg, cvec, Wa, ba, MOD);
    attn_main_f16<<<dim3(S / 128, NH, B), 256>>>(Q, K, V, MOD, mask, CTX);

    // causal branch (blend fused into out-proj epilogue)
    gemm_tc<__half, __half, false><<<gN3, 256>>>(HSh, caInH, ca_in_b, QKV3, MS, 3 * H, H, nullptr, 0.f, 0.f);
    attn_big_f16<<<dim3(S / 32, BH, B), 256>>>(QKV3, QKV3 + H, QKV3 + 2 * H, 3 * H, T1, 0.0625f);
    gemm_tc<__half, float, true><<<gN1, 256>>>(T1, caOwH, ca_ob, CTX, MS, H, H, CTX, 0.3f, 0.7f);

    // metacognitive branch (blend fused)
    gemm_tc<float, __half, false><<<gN3, 256>>>(CTX, maInH, ma_in_b, QKV3, MS, 3 * H, H, nullptr, 0.f, 0.f);
    attn_big_f16<<<dim3(S / 32, BH, B), 256>>>(QKV3, QKV3 + H, QKV3 + 2 * H, 3 * H, T1, 0.0625f);
    gemm_tc<__half, float, true><<<gN1, 256>>>(T1, maOwH, ma_ob, CTX, MS, H, H, CTX, 0.85f, 0.15f);

    // output projection
    gemm_tc<float, float, false><<<gN1, 256>>>(CTX, WoH, bo, (float*)d_out, MS, H, H, nullptr, 0.f, 0.f);
}

// round 12
// speedup vs baseline: 1.6940x; 1.1488x over previous
#include <cuda_runtime.h>
#include <cuda_fp16.h>
#include <stdint.h>
#include <math.h>

#define B 2
#define S 2048
#define H 1024
#define NH 16
#define HD 64
#define BH 4
#define BD 256
#define MS (B*S)   /* 4096 rows */
#define MHH (H*H)  /* 1048576 */

// ---------------- scratch (static device globals; no allocations) ----------------
__device__ __half g_Q[MS * H];
__device__ __half g_K[MS * H];
__device__ __half g_V[MS * H];
__device__ float  g_MOD[MS * NH];
__device__ float  g_CTX[MS * H];
__device__ __half g_QKV3[MS * 3 * H];
__device__ __half g_T1[MS * H];
__device__ __half g_HSh[MS * H];       // hs in half
__device__ __half g_WH[12 * MHH];      // all weights in half

// ---------------- helpers ----------------
__device__ __forceinline__ uint32_t cvta_s(const void* p) {
    return (uint32_t)__cvta_generic_to_shared(p);
}
__device__ __forceinline__ uint32_t packh2(float a, float b) {
    __half2 h = __floats2half2_rn(a, b);
    return *reinterpret_cast<uint32_t*>(&h);
}
__device__ __forceinline__ void ldsm_x4(uint32_t addr, uint32_t* r) {
    asm volatile("ldmatrix.sync.aligned.m8n8.x4.shared.b16 {%0,%1,%2,%3}, [%4];"
        : "=r"(r[0]), "=r"(r[1]), "=r"(r[2]), "=r"(r[3]) : "r"(addr));
}
__device__ __forceinline__ void ldsm_x4_t(uint32_t addr, uint32_t* r) {
    asm volatile("ldmatrix.sync.aligned.m8n8.x4.trans.shared.b16 {%0,%1,%2,%3}, [%4];"
        : "=r"(r[0]), "=r"(r[1]), "=r"(r[2]), "=r"(r[3]) : "r"(addr));
}
__device__ __forceinline__ void ldsm_x2(uint32_t addr, uint32_t* r) {
    asm volatile("ldmatrix.sync.aligned.m8n8.x2.shared.b16 {%0,%1}, [%2];"
        : "=r"(r[0]), "=r"(r[1]) : "r"(addr));
}
__device__ __forceinline__ void mma_f16(float* d, const uint32_t* a, const uint32_t* b) {
    asm volatile(
        "mma.sync.aligned.m16n8k16.row.col.f32.f16.f16.f32 "
        "{%0,%1,%2,%3}, {%4,%5,%6,%7}, {%8,%9}, {%0,%1,%2,%3};"
        : "+f"(d[0]), "+f"(d[1]), "+f"(d[2]), "+f"(d[3])
        : "r"(a[0]), "r"(a[1]), "r"(a[2]), "r"(a[3]), "r"(b[0]), "r"(b[1]));
}

// ---------------- fp32 -> fp16 convert (vectorized, 8 elems/thread) ----------------
__global__ __launch_bounds__(256) void cvt_h(const float* __restrict__ src,
                                             __half* __restrict__ dst, int n)
{
    int i = (blockIdx.x * 256 + threadIdx.x) * 8;
    if (i < n) {
        float4 a = *(const float4*)(src + i);
        float4 b = *(const float4*)(src + i + 4);
        uint4 o;
        o.x = packh2(a.x, a.y); o.y = packh2(a.z, a.w);
        o.z = packh2(b.x, b.y); o.w = packh2(b.z, b.w);
        *(uint4*)(dst + i) = o;
    }
}

// ---------------- FP16 tensor-core GEMM (double-buffered smem) ----------------
#define A_BUF_B 10240   /* 128*40*2 bytes */
#define B_BUF_B 8704    /* 32*136*2 bytes */

template<typename TA, typename TO, bool BLEND>
__global__ __launch_bounds__(256) void gemm_tc(
    const TA* __restrict__ A, const __half* __restrict__ W,
    const float* __restrict__ bias, TO* __restrict__ C,
    int M, int N, int K,
    const float* __restrict__ bld, float wa, float wb)
{
    __shared__ __half As[2][128][40];    // row stride 80B
    __shared__ __half Bs[2][32][136];    // row stride 272B

    int tid = threadIdx.x, warp = tid >> 5, lane = tid & 31;
    int wm = (warp >> 2) * 64, wn = (warp & 3) * 32;
    int m0 = blockIdx.y * 128, n0 = blockIdx.x * 128;
    int gid = lane >> 2, tig = lane & 3;

    float acc[4][4][4];
#pragma unroll
    for (int mt = 0; mt < 4; mt++)
#pragma unroll
        for (int nt = 0; nt < 4; nt++)
#pragma unroll
            for (int r = 0; r < 4; r++) acc[mt][nt][r] = 0.f;

    int aRow[4], aCol[4], bRow[4], bCol[4];
#pragma unroll
    for (int i = 0; i < 4; i++) {
        int fi = tid + 256 * i;
        aRow[i] = fi >> 3;  aCol[i] = (fi & 7) * 4;
        bRow[i] = fi >> 5;  bCol[i] = (fi & 31) * 4;
    }

    int lr = ((lane >> 3) & 1) * 8 + (lane & 7);
    int lc = (lane >> 4) * 8;
    uint32_t a_addr[4], b_addr[2];
#pragma unroll
    for (int mt = 0; mt < 4; mt++)
        a_addr[mt] = cvta_s(&As[0][wm + mt * 16 + lr][lc]);
#pragma unroll
    for (int ntp = 0; ntp < 2; ntp++)
        b_addr[ntp] = cvta_s(&Bs[0][lr][wn + ntp * 16 + lc]);

    auto loadTile = [&](int kb, uint2* aPk, uint2* bPk) {
#pragma unroll
        for (int i = 0; i < 4; i++) {
            if constexpr (sizeof(TA) == 4) {
                float4 av = *(const float4*)((const float*)A + (size_t)(m0 + aRow[i]) * K + kb + aCol[i]);
                aPk[i].x = packh2(av.x, av.y); aPk[i].y = packh2(av.z, av.w);
            } else {
                aPk[i] = *(const uint2*)((const __half*)A + (size_t)(m0 + aRow[i]) * K + kb + aCol[i]);
            }
            bPk[i] = *(const uint2*)(W + (size_t)(kb + bRow[i]) * N + n0 + bCol[i]);
        }
    };
    auto storeTile = [&](int buf, const uint2* aPk, const uint2* bPk) {
#pragma unroll
        for (int i = 0; i < 4; i++) {
            *(uint2*)&As[buf][aRow[i]][aCol[i]] = aPk[i];
            *(uint2*)&Bs[buf][bRow[i]][bCol[i]] = bPk[i];
        }
    };

    int ntiles = K / 32;
    uint2 aPk[4], bPk[4];
    loadTile(0, aPk, bPk);
    storeTile(0, aPk, bPk);
    __syncthreads();
    if (ntiles > 1) loadTile(32, aPk, bPk);

    for (int kt = 0; kt < ntiles; kt++) {
        int buf = kt & 1;
        uint32_t aoff = (uint32_t)buf * A_BUF_B;
        uint32_t boff = (uint32_t)buf * B_BUF_B;
#pragma unroll
        for (int q = 0; q < 2; q++) {
            int kq = q * 16;
            uint32_t af[4][4], bu0[4], bu1[4];
#pragma unroll
            for (int mt = 0; mt < 4; mt++) ldsm_x4(a_addr[mt] + aoff + kq * 2, af[mt]);
            ldsm_x4_t(b_addr[0] + boff + kq * 272, bu0);
            ldsm_x4_t(b_addr[1] + boff + kq * 272, bu1);
#pragma unroll
            for (int mt = 0; mt < 4; mt++) {
                mma_f16(acc[mt][0], af[mt], bu0 + 0);
                mma_f16(acc[mt][1], af[mt], bu0 + 2);
                mma_f16(acc[mt][2], af[mt], bu1 + 0);
                mma_f16(acc[mt][3], af[mt], bu1 + 2);
            }
        }
        if (kt + 1 < ntiles) {
            storeTile(buf ^ 1, aPk, bPk);
            __syncthreads();
            if (kt + 2 < ntiles) loadTile((kt + 2) * 32, aPk, bPk);
        }
    }

#pragma unroll
    for (int mt = 0; mt < 4; mt++) {
        int r0 = m0 + wm + mt * 16 + gid;
#pragma unroll
        for (int nt = 0; nt < 4; nt++) {
            int c = n0 + wn + nt * 8 + tig * 2;
            float b0v = bias[c], b1v = bias[c + 1];
            float e00 = acc[mt][nt][0] + b0v, e01 = acc[mt][nt][1] + b1v;
            float e10 = acc[mt][nt][2] + b0v, e11 = acc[mt][nt][3] + b1v;
            if constexpr (BLEND) {
                float2 x0 = *(const float2*)(bld + (size_t)r0 * N + c);
                float2 x1 = *(const float2*)(bld + (size_t)(r0 + 8) * N + c);
                e00 = x0.x * wa + e00 * wb; e01 = x0.y * wa + e01 * wb;
                e10 = x1.x * wa + e10 * wb; e11 = x1.y * wa + e11 * wb;
            }
            if constexpr (sizeof(TO) == 2) {
                *(uint32_t*)((__half*)C + (size_t)r0 * N + c) = packh2(e00, e01);
                *(uint32_t*)((__half*)C + (size_t)(r0 + 8) * N + c) = packh2(e10, e11);
            } else {
                float2 v0, v1;
                v0.x = e00; v0.y = e01; v1.x = e10; v1.y = e11;
                *(float2*)((float*)C + (size_t)r0 * N + c) = v0;
                *(float2*)((float*)C + (size_t)(r0 + 8) * N + c) = v1;
            }
        }
    }
}

// ---------------- modulation (smem-tiled): sigmoid(hs@Wg + bg + cvec@Wa + ba) ----------------
__global__ __launch_bounds__(256) void gatemod2(
    const float* __restrict__ hs, const float* __restrict__ Wg,
    const float* __restrict__ bg, const float* __restrict__ cvec,
    const float* __restrict__ Wa, const float* __restrict__ ba,
    float* __restrict__ MODo)
{
    __shared__ float Wgs[64][16];
    __shared__ float hss[16][68];
    __shared__ float awS[16];

    int tid = threadIdx.x;
    int m0 = blockIdx.x * 16;
    int r = tid >> 4, n = tid & 15;

    if (tid < 16) {
        float aw = ba[tid] + bg[tid];
#pragma unroll
        for (int k = 0; k < 16; k++) aw += cvec[k] * Wa[k * 16 + tid];
        awS[tid] = aw;
    }

    float acc = 0.f;
    for (int kt = 0; kt < H; kt += 64) {
        __syncthreads();
        *(float4*)&((float*)Wgs)[tid * 4] = *(const float4*)&Wg[kt * 16 + tid * 4];
        int r2 = tid >> 4, k2 = (tid & 15) * 4;
        *(float4*)&hss[r2][k2] = *(const float4*)&hs[(size_t)(m0 + r2) * H + kt + k2];
        __syncthreads();
#pragma unroll
        for (int k = 0; k < 64; k++) acc += hss[r][k] * Wgs[k][n];
    }
    float x = acc + awS[n];
    MODo[(size_t)(m0 + r) * NH + n] = 1.f / (1.f + __expf(-x));
}

// ---------------- main attention (fp16 TC): 16 heads, hd=64 ----------------
__global__ __launch_bounds__(256) void attn_main_f16(
    const __half* __restrict__ Qb, const __half* __restrict__ Kb,
    const __half* __restrict__ Vb, const float* __restrict__ MODb,
    const int* __restrict__ maskb, float* __restrict__ Ob)
{
    __shared__ __half Ks[32][72];   // [key][d], 144B stride
    __shared__ __half Vs[32][72];
    __shared__ float Madd[32];

    int tid = threadIdx.x, lane = tid & 31, warp = tid >> 5;
    int gid = lane >> 2, tig = lane & 3;
    int q0 = blockIdx.x * 128, h = blockIdx.y, b = blockIdx.z;
    int qw = q0 + warp * 16;

    uint32_t qf[4][4];
    const __half* Qg = Qb + (size_t)(b * S + qw) * H + h * HD;
#pragma unroll
    for (int s = 0; s < 4; s++) {
        int c0 = s * 16 + 2 * tig;
        qf[s][0] = *(const uint32_t*)(Qg + (size_t)gid * H + c0);
        qf[s][1] = *(const uint32_t*)(Qg + (size_t)(gid + 8) * H + c0);
        qf[s][2] = *(const uint32_t*)(Qg + (size_t)gid * H + c0 + 8);
        qf[s][3] = *(const uint32_t*)(Qg + (size_t)(gid + 8) * H + c0 + 8);
    }
    float mod0 = MODb[(size_t)(b * S + qw + gid) * NH + h] * 0.125f;
    float mod1 = MODb[(size_t)(b * S + qw + gid + 8) * NH + h] * 0.125f;

    uint32_t kaddr[2], vaddr[4];
#pragma unroll
    for (int ntp = 0; ntp < 2; ntp++)
        kaddr[ntp] = cvta_s(&Ks[(ntp * 2 + (lane >> 4)) * 8 + (lane & 7)][((lane >> 3) & 1) * 8]);
#pragma unroll
    for (int nfp = 0; nfp < 4; nfp++)
        vaddr[nfp] = cvta_s(&Vs[((lane >> 3) & 1) * 8 + (lane & 7)][(nfp * 2 + (lane >> 4)) * 8]);

    int cr = tid >> 3, cs = (tid & 7) * 8;
    const __half* KgB = Kb + (size_t)(b * S) * H + h * HD;
    const __half* VgB = Vb + (size_t)(b * S) * H + h * HD;

    float m0v = -1e30f, m1v = -1e30f, l0 = 0.f, l1 = 0.f;
    float oacc[8][4];
#pragma unroll
    for (int nf = 0; nf < 8; nf++)
#pragma unroll
        for (int r = 0; r < 4; r++) oacc[nf][r] = 0.f;

    for (int kt = 0; kt < S; kt += 32) {
        __syncthreads();
        *(uint4*)&Ks[cr][cs] = *(const uint4*)(KgB + (size_t)(kt + cr) * H + cs);
        *(uint4*)&Vs[cr][cs] = *(const uint4*)(VgB + (size_t)(kt + cr) * H + cs);
        if (tid < 32) Madd[tid] = maskb[b * S + kt + tid] ? 0.f : -1e30f;
        __syncthreads();

        float sc[4][4];
#pragma unroll
        for (int nf = 0; nf < 4; nf++)
#pragma unroll
            for (int r = 0; r < 4; r++) sc[nf][r] = 0.f;
#pragma unroll
        for (int s = 0; s < 4; s++) {
            uint32_t ku0[4], ku1[4];
            ldsm_x4(kaddr[0] + s * 32, ku0);
            ldsm_x4(kaddr[1] + s * 32, ku1);
            mma_f16(sc[0], qf[s], ku0 + 0);
            mma_f16(sc[1], qf[s], ku0 + 2);
            mma_f16(sc[2], qf[s], ku1 + 0);
            mma_f16(sc[3], qf[s], ku1 + 2);
        }

        float mx0 = -1e30f, mx1 = -1e30f;
#pragma unroll
        for (int nf = 0; nf < 4; nf++) {
            float ma = Madd[nf * 8 + 2 * tig], mb2 = Madd[nf * 8 + 2 * tig + 1];
            sc[nf][0] = sc[nf][0] * mod0 + ma;
            sc[nf][1] = sc[nf][1] * mod0 + mb2;
            sc[nf][2] = sc[nf][2] * mod1 + ma;
            sc[nf][3] = sc[nf][3] * mod1 + mb2;
            mx0 = fmaxf(mx0, fmaxf(sc[nf][0], sc[nf][1]));
            mx1 = fmaxf(mx1, fmaxf(sc[nf][2], sc[nf][3]));
        }
        mx0 = fmaxf(mx0, __shfl_xor_sync(0xffffffffu, mx0, 1));
        mx0 = fmaxf(mx0, __shfl_xor_sync(0xffffffffu, mx0, 2));
        mx1 = fmaxf(mx1, __shfl_xor_sync(0xffffffffu, mx1, 1));
        mx1 = fmaxf(mx1, __shfl_xor_sync(0xffffffffu, mx1, 2));
        float mn0 = fmaxf(m0v, mx0), mn1 = fmaxf(m1v, mx1);
        float al0 = __expf(m0v - mn0), al1 = __expf(m1v - mn1);
        float ps0 = 0.f, ps1 = 0.f;
        uint32_t pva[2][4];
#pragma unroll
        for (int nf = 0; nf < 4; nf++) {
            float p00 = __expf(sc[nf][0] - mn0), p01 = __expf(sc[nf][1] - mn0);
            float p10 = __expf(sc[nf][2] - mn1), p11 = __expf(sc[nf][3] - mn1);
            ps0 += p00 + p01; ps1 += p10 + p11;
            int s2 = nf >> 1, hi = (nf & 1) * 2;
            pva[s2][hi]     = packh2(p00, p01);
            pva[s2][hi + 1] = packh2(p10, p11);
        }
        ps0 += __shfl_xor_sync(0xffffffffu, ps0, 1);
        ps0 += __shfl_xor_sync(0xffffffffu, ps0, 2);
        ps1 += __shfl_xor_sync(0xffffffffu, ps1, 1);
        ps1 += __shfl_xor_sync(0xffffffffu, ps1, 2);
        l0 = l0 * al0 + ps0; l1 = l1 * al1 + ps1;
        m0v = mn0; m1v = mn1;
#pragma unroll
        for (int nf = 0; nf < 8; nf++) {
            oacc[nf][0] *= al0; oacc[nf][1] *= al0;
            oacc[nf][2] *= al1; oacc[nf][3] *= al1;
        }

#pragma unroll
        for (int s2 = 0; s2 < 2; s2++) {
#pragma unroll
            for (int nfp = 0; nfp < 4; nfp++) {
                uint32_t vu[4];
                ldsm_x4_t(vaddr[nfp] + s2 * 16 * 144, vu);
                mma_f16(oacc[nfp * 2],     pva[s2], vu + 0);
                mma_f16(oacc[nfp * 2 + 1], pva[s2], vu + 2);
            }
        }
    }

    float inv0 = 1.f / l0, inv1 = 1.f / l1;
    float* Og = Ob + (size_t)(b * S + qw) * H + h * HD;
#pragma unroll
    for (int nf = 0; nf < 8; nf++) {
        int c = nf * 8 + 2 * tig;
        float2 v0, v1;
        v0.x = oacc[nf][0] * inv0; v0.y = oacc[nf][1] * inv0;
        v1.x = oacc[nf][2] * inv1; v1.y = oacc[nf][3] * inv1;
        *(float2*)(Og + (size_t)gid * H + c) = v0;
        *(float2*)(Og + (size_t)(gid + 8) * H + c) = v1;
    }
}

// ---------------- big-head attention (fp16 TC): 4 heads, hd=256, 64q/512t ----------------
// 16 warps 4(m) x 4(n); halves K/V L2 traffic vs 32q blocks
__global__ __launch_bounds__(512) void attn_big_f16(
    const __half* __restrict__ Qb, const __half* __restrict__ Kb,
    const __half* __restrict__ Vb, int ld, __half* __restrict__ Ob, float scale)
{
    __shared__ __half Ks[32][264];   // [key][d], 528B stride
    __shared__ __half Vs[32][264];
    __shared__ float SP[64][36];
    __shared__ __half SPh[64][40];
    __shared__ float Mst[64], Lst[64], Alp[64];

    int tid = threadIdx.x, lane = tid & 31, warp = tid >> 5;
    int gid = lane >> 2, tig = lane & 3;
    int wm = warp >> 2, wn = warp & 3;      // wm 0..3 (64 q-rows), wn 0..3
    int q0 = blockIdx.x * 64, h = blockIdx.y, b = blockIdx.z;

    uint32_t qf[16][4];
    const __half* Qg = Qb + (size_t)(b * S + q0 + wm * 16) * ld + h * BD;
#pragma unroll
    for (int s = 0; s < 16; s++) {
        int c0 = s * 16 + 2 * tig;
        qf[s][0] = *(const uint32_t*)(Qg + (size_t)gid * ld + c0);
        qf[s][1] = *(const uint32_t*)(Qg + (size_t)(gid + 8) * ld + c0);
        qf[s][2] = *(const uint32_t*)(Qg + (size_t)gid * ld + c0 + 8);
        qf[s][3] = *(const uint32_t*)(Qg + (size_t)(gid + 8) * ld + c0 + 8);
    }
    if (tid < 64) { Mst[tid] = -1e30f; Lst[tid] = 0.f; }

    uint32_t kaddr = cvta_s(&Ks[wn * 8 + (lane & 7)][((lane >> 3) & 1) * 8]);
    uint32_t paddr = cvta_s(&SPh[wm * 16 + ((lane >> 3) & 1) * 8 + (lane & 7)][(lane >> 4) * 8]);
    uint32_t vaddr = cvta_s(&Vs[((lane >> 3) & 1) * 8 + (lane & 7)][wn * 64 + (lane >> 4) * 8]);

    const __half* KgB = Kb + (size_t)(b * S) * ld + h * BD;
    const __half* VgB = Vb + (size_t)(b * S) * ld + h * BD;

    float oacc[8][4];
#pragma unroll
    for (int nf = 0; nf < 8; nf++)
#pragma unroll
        for (int r = 0; r < 4; r++) oacc[nf][r] = 0.f;

    for (int kt = 0; kt < S; kt += 32) {
        __syncthreads();
#pragma unroll
        for (int it = 0; it < 2; it++) {
            int idx = tid + it * 512;
            int r = idx >> 5, sg = (idx & 31) * 8;
            *(uint4*)&Ks[r][sg] = *(const uint4*)(KgB + (size_t)(kt + r) * ld + sg);
            *(uint4*)&Vs[r][sg] = *(const uint4*)(VgB + (size_t)(kt + r) * ld + sg);
        }
        __syncthreads();

        float sc[4] = {0.f, 0.f, 0.f, 0.f};
#pragma unroll
        for (int s = 0; s < 16; s++) {
            uint32_t ku[2];
            ldsm_x2(kaddr + s * 32, ku);
            mma_f16(sc, qf[s], ku);
        }
        {
            int rw = wm * 16 + gid, c = wn * 8 + 2 * tig;
            float2 v;
            v.x = sc[0] * scale; v.y = sc[1] * scale;
            *(float2*)&SP[rw][c] = v;
            v.x = sc[2] * scale; v.y = sc[3] * scale;
            *(float2*)&SP[rw + 8][c] = v;
        }
        __syncthreads();

        {
            int row = tid >> 3, c0 = (tid & 7) * 4;
            float4 sv = *(const float4*)&SP[row][c0];
            float mx = fmaxf(fmaxf(sv.x, sv.y), fmaxf(sv.z, sv.w));
            mx = fmaxf(mx, __shfl_xor_sync(0xffffffffu, mx, 1));
            mx = fmaxf(mx, __shfl_xor_sync(0xffffffffu, mx, 2));
            mx = fmaxf(mx, __shfl_xor_sync(0xffffffffu, mx, 4));
            float mold = Mst[row];
            float mnew = fmaxf(mold, mx);
            float p0 = __expf(sv.x - mnew), p1 = __expf(sv.y - mnew);
            float p2 = __expf(sv.z - mnew), p3 = __expf(sv.w - mnew);
            float ps = p0 + p1 + p2 + p3;
            ps += __shfl_xor_sync(0xffffffffu, ps, 1);
            ps += __shfl_xor_sync(0xffffffffu, ps, 2);
            ps += __shfl_xor_sync(0xffffffffu, ps, 4);
            if ((tid & 7) == 0) {
                float al = __expf(mold - mnew);
                Mst[row] = mnew; Lst[row] = Lst[row] * al + ps; Alp[row] = al;
            }
            uint2 pu; pu.x = packh2(p0, p1); pu.y = packh2(p2, p3);
            *(uint2*)&SPh[row][c0] = pu;
        }
        __syncthreads();

        float al0 = Alp[wm * 16 + gid], al1 = Alp[wm * 16 + gid + 8];
#pragma unroll
        for (int nf = 0; nf < 8; nf++) {
            oacc[nf][0] *= al0; oacc[nf][1] *= al0;
            oacc[nf][2] *= al1; oacc[nf][3] *= al1;
        }

#pragma unroll
        for (int s2 = 0; s2 < 2; s2++) {
            uint32_t pa[4];
            ldsm_x4(paddr + s2 * 32, pa);
#pragma unroll
            for (int nfp = 0; nfp < 4; nfp++) {
                uint32_t vu[4];
                ldsm_x4_t(vaddr + s2 * 8448 + nfp * 32, vu);
                mma_f16(oacc[nfp * 2],     pa, vu + 0);
                mma_f16(oacc[nfp * 2 + 1], pa, vu + 2);
            }
        }
    }

    float inv0 = 1.f / Lst[wm * 16 + gid], inv1 = 1.f / Lst[wm * 16 + gid + 8];
    __half* Og = Ob + (size_t)(b * S + q0 + wm * 16) * H + h * BD;
#pragma unroll
    for (int nf = 0; nf < 8; nf++) {
        int c = wn * 64 + nf * 8 + 2 * tig;
        *(uint32_t*)(Og + (size_t)gid * H + c) =
            packh2(oacc[nf][0] * inv0, oacc[nf][1] * inv0);
        *(uint32_t*)(Og + (size_t)(gid + 8) * H + c) =
            packh2(oacc[nf][2] * inv1, oacc[nf][3] * inv1);
    }
}

// ---------------- launch ----------------
extern "C" void kernel_launch(void* const* d_in, const int* in_sizes, int n_in,
                              void* d_out, int out_size)
{
    (void)in_sizes; (void)n_in; (void)out_size;
    const float* hs      = (const float*)d_in[0];
    const int*   mask    = (const int*)  d_in[1];
    const float* cvec    = (const float*)d_in[2];
    const float* Wq      = (const float*)d_in[3];
    const float* bq      = (const float*)d_in[4];
    const float* Wk      = (const float*)d_in[5];
    const float* bk      = (const float*)d_in[6];
    const float* Wv      = (const float*)d_in[7];
    const float* bv      = (const float*)d_in[8];
    const float* Wg      = (const float*)d_in[9];
    const float* bg      = (const float*)d_in[10];
    const float* Wa      = (const float*)d_in[11];
    const float* ba      = (const float*)d_in[12];
    const float* ca_in_w = (const float*)d_in[13];
    const float* ca_in_b = (const float*)d_in[14];
    const float* ca_ow   = (const float*)d_in[15];
    const float* ca_ob   = (const float*)d_in[16];
    const float* ma_in_w = (const float*)d_in[17];
    const float* ma_in_b = (const float*)d_in[18];
    const float* ma_ow   = (const float*)d_in[19];
    const float* ma_ob   = (const float*)d_in[20];
    const float* Wo      = (const float*)d_in[21];
    const float* bo      = (const float*)d_in[22];

    __half *Q, *K, *V, *QKV3, *T1, *HSh, *WH;
    float *MOD, *CTX;
    cudaGetSymbolAddress((void**)&Q, g_Q);
    cudaGetSymbolAddress((void**)&K, g_K);
    cudaGetSymbolAddress((void**)&V, g_V);
    cudaGetSymbolAddress((void**)&MOD, g_MOD);
    cudaGetSymbolAddress((void**)&CTX, g_CTX);
    cudaGetSymbolAddress((void**)&QKV3, g_QKV3);
    cudaGetSymbolAddress((void**)&T1, g_T1);
    cudaGetSymbolAddress((void**)&HSh, g_HSh);
    cudaGetSymbolAddress((void**)&WH, g_WH);

    // half-weight pool offsets
    __half* WqH = WH + 0 * (size_t)MHH;
    __half* WkH = WH + 1 * (size_t)MHH;
    __half* WvH = WH + 2 * (size_t)MHH;
    __half* caInH = WH + 3 * (size_t)MHH;    // 3 MHH
    __half* caOwH = WH + 6 * (size_t)MHH;
    __half* maInH = WH + 7 * (size_t)MHH;    // 3 MHH
    __half* maOwH = WH + 10 * (size_t)MHH;
    __half* WoH = WH + 11 * (size_t)MHH;

    // converts (8 elems/thread, 2048 elems/block)
    cvt_h<<<MS * H / 2048, 256>>>(hs, HSh, MS * H);
    cvt_h<<<MHH / 2048, 256>>>(Wq, WqH, MHH);
    cvt_h<<<MHH / 2048, 256>>>(Wk, WkH, MHH);
    cvt_h<<<MHH / 2048, 256>>>(Wv, WvH, MHH);
    cvt_h<<<3 * MHH / 2048, 256>>>(ca_in_w, caInH, 3 * MHH);
    cvt_h<<<MHH / 2048, 256>>>(ca_ow, caOwH, MHH);
    cvt_h<<<3 * MHH / 2048, 256>>>(ma_in_w, maInH, 3 * MHH);
    cvt_h<<<MHH / 2048, 256>>>(ma_ow, maOwH, MHH);
    cvt_h<<<MHH / 2048, 256>>>(Wo, WoH, MHH);

    dim3 gN1(H / 128, MS / 128);
    dim3 gN3(3 * H / 128, MS / 128);

    // main attention path
    gemm_tc<__half, __half, false><<<gN1, 256>>>(HSh, WqH, bq, Q, MS, H, H, nullptr, 0.f, 0.f);
    gemm_tc<__half, __half, false><<<gN1, 256>>>(HSh, WkH, bk, K, MS, H, H, nullptr, 0.f, 0.f);
    gemm_tc<__half, __half, false><<<gN1, 256>>>(HSh, WvH, bv, V, MS, H, H, nullptr, 0.f, 0.f);
    gatemod2<<<MS / 16, 256>>>(hs, Wg, bg, cvec, Wa, ba, MOD);
    attn_main_f16<<<dim3(S / 128, NH, B), 256>>>(Q, K, V, MOD, mask, CTX);

    // causal branch (blend fused into out-proj epilogue)
    gemm_tc<__half, __half, false><<<gN3, 256>>>(HSh, caInH, ca_in_b, QKV3, MS, 3 * H, H, nullptr, 0.f, 0.f);
    attn_big_f16<<<dim3(S / 64, BH, B), 512>>>(QKV3, QKV3 + H, QKV3 + 2 * H, 3 * H, T1, 0.0625f);
    gemm_tc<__half, float, true><<<gN1, 256>>>(T1, caOwH, ca_ob, CTX, MS, H, H, CTX, 0.3f, 0.7f);

    // metacognitive branch (blend fused)
    gemm_tc<float, __half, false><<<gN3, 256>>>(CTX, maInH, ma_in_b, QKV3, MS, 3 * H, H, nullptr, 0.f, 0.f);
    attn_big_f16<<<dim3(S / 64, BH, B), 512>>>(QKV3, QKV3 + H, QKV3 + 2 * H, 3 * H, T1, 0.0625f);
    gemm_tc<__half, float, true><<<gN1, 256>>>(T1, maOwH, ma_ob, CTX, MS, H, H, CTX, 0.85f, 0.15f);

    // output projection
    gemm_tc<float, float, false><<<gN1, 256>>>(CTX, WoH, bo, (float*)d_out, MS, H, H, nullptr, 0.f, 0.f);
}

// round 14
// speedup vs baseline: 1.8095x; 1.0681x over previous
#include <cuda_runtime.h>
#include <cuda_fp16.h>
#include <stdint.h>
#include <math.h>

#define B 2
#define S 2048
#define H 1024
#define NH 16
#define HD 64
#define BH 4
#define BD 256
#define MS (B*S)   /* 4096 rows */
#define MHH (H*H)  /* 1048576 */

// ---------------- scratch (static device globals; no allocations) ----------------
__device__ __half g_Q[MS * H];
__device__ __half g_K[MS * H];
__device__ __half g_V[MS * H];
__device__ float  g_MOD[MS * NH];
__device__ __half g_CTX[MS * H];
__device__ __half g_QKV3[MS * 3 * H];
__device__ __half g_T1[MS * H];
__device__ __half g_HSh[MS * H];       // hs in half
__device__ __half g_WH[12 * MHH];      // all weights in half

// ---------------- helpers ----------------
__device__ __forceinline__ uint32_t cvta_s(const void* p) {
    return (uint32_t)__cvta_generic_to_shared(p);
}
__device__ __forceinline__ uint32_t packh2(float a, float b) {
    __half2 h = __floats2half2_rn(a, b);
    return *reinterpret_cast<uint32_t*>(&h);
}
__device__ __forceinline__ float2 h2f2(uint32_t u) {
    __half2 h = *reinterpret_cast<__half2*>(&u);
    return __half22float2(h);
}
__device__ __forceinline__ void ldsm_x4(uint32_t addr, uint32_t* r) {
    asm volatile("ldmatrix.sync.aligned.m8n8.x4.shared.b16 {%0,%1,%2,%3}, [%4];"
        : "=r"(r[0]), "=r"(r[1]), "=r"(r[2]), "=r"(r[3]) : "r"(addr));
}
__device__ __forceinline__ void ldsm_x4_t(uint32_t addr, uint32_t* r) {
    asm volatile("ldmatrix.sync.aligned.m8n8.x4.trans.shared.b16 {%0,%1,%2,%3}, [%4];"
        : "=r"(r[0]), "=r"(r[1]), "=r"(r[2]), "=r"(r[3]) : "r"(addr));
}
__device__ __forceinline__ void ldsm_x2(uint32_t addr, uint32_t* r) {
    asm volatile("ldmatrix.sync.aligned.m8n8.x2.shared.b16 {%0,%1}, [%2];"
        : "=r"(r[0]), "=r"(r[1]) : "r"(addr));
}
__device__ __forceinline__ void mma_f16(float* d, const uint32_t* a, const uint32_t* b) {
    asm volatile(
        "mma.sync.aligned.m16n8k16.row.col.f32.f16.f16.f32 "
        "{%0,%1,%2,%3}, {%4,%5,%6,%7}, {%8,%9}, {%0,%1,%2,%3};"
        : "+f"(d[0]), "+f"(d[1]), "+f"(d[2]), "+f"(d[3])
        : "r"(a[0]), "r"(a[1]), "r"(a[2]), "r"(a[3]), "r"(b[0]), "r"(b[1]));
}
__device__ __forceinline__ void cp16(uint32_t dst, const void* src) {
    asm volatile("cp.async.cg.shared.global [%0], [%1], 16;" :: "r"(dst), "l"(src));
}
__device__ __forceinline__ void cp_commit() {
    asm volatile("cp.async.commit_group;" ::: "memory");
}
__device__ __forceinline__ void cp_wait2() {
    asm volatile("cp.async.wait_group 2;" ::: "memory");
}
__device__ __forceinline__ void cp_wait1() {
    asm volatile("cp.async.wait_group 1;" ::: "memory");
}
__device__ __forceinline__ void cp_wait0() {
    asm volatile("cp.async.wait_group 0;" ::: "memory");
}

// ---------------- fp32 -> fp16 convert (vectorized, 8 elems/thread) ----------------
__global__ __launch_bounds__(256) void cvt_h(const float* __restrict__ src,
                                             __half* __restrict__ dst, int n)
{
    int i = (blockIdx.x * 256 + threadIdx.x) * 8;
    if (i < n) {
        float4 a = *(const float4*)(src + i);
        float4 b = *(const float4*)(src + i + 4);
        uint4 o;
        o.x = packh2(a.x, a.y); o.y = packh2(a.z, a.w);
        o.z = packh2(b.x, b.y); o.w = packh2(b.z, b.w);
        *(uint4*)(dst + i) = o;
    }
}

// ---------------- FP16 GEMM: 4-stage cp.async pipeline, 1 sync/iter ----------------
// block 128x128x32, 8 warps 2x4, warp tile 64x32.  A,W half; out TO; opt half blend.
#define STG_B 18944u   /* A 128*80 + B 32*272 bytes */

template<typename TO, bool BLEND>
__global__ __launch_bounds__(256) void gemm_tc(
    const __half* __restrict__ A, const __half* __restrict__ W,
    const float* __restrict__ bias, TO* __restrict__ C,
    int M, int N, int K,
    const __half* __restrict__ bld, float wa, float wb)
{
    extern __shared__ char smx[];
    uint32_t smb = cvta_s(smx);

    int tid = threadIdx.x, warp = tid >> 5, lane = tid & 31;
    int wm = (warp >> 2) * 64, wn = (warp & 3) * 32;
    int m0 = blockIdx.y * 128, n0 = blockIdx.x * 128;
    int gid = lane >> 2, tig = lane & 3;

    float acc[4][4][4];
#pragma unroll
    for (int mt = 0; mt < 4; mt++)
#pragma unroll
        for (int nt = 0; nt < 4; nt++)
#pragma unroll
            for (int r = 0; r < 4; r++) acc[mt][nt][r] = 0.f;

    // cp.async mappings (512 x 16B segs each for A and B)
    int aRow[2], aSeg[2];     // A tile 128 rows x 32 halves: 4 segs of 16B per row
#pragma unroll
    for (int i = 0; i < 2; i++) {
        int idx = tid + 256 * i;
        aRow[i] = idx >> 2; aSeg[i] = (idx & 3) * 8;
    }
    int bRow[2], bSeg[2];     // B tile 32 rows x 128 halves: 16 segs per row
#pragma unroll
    for (int i = 0; i < 2; i++) {
        int idx = tid + 256 * i;
        bRow[i] = idx >> 4; bSeg[i] = (idx & 15) * 8;
    }

    // ldmatrix lane addrs (stage 0 base)
    int lr = ((lane >> 3) & 1) * 8 + (lane & 7);
    int lc16 = (lane >> 4) * 16;   // bytes
    uint32_t a_addr[4], b_addr[2];
#pragma unroll
    for (int mt = 0; mt < 4; mt++)
        a_addr[mt] = smb + (uint32_t)(wm + mt * 16 + lr) * 80 + lc16;
#pragma unroll
    for (int ntp = 0; ntp < 2; ntp++)
        b_addr[ntp] = smb + 10240 + (uint32_t)lr * 272 + (uint32_t)(wn + ntp * 16) * 2 + lc16;

    auto cpTile = [&](int stage, int kb) {
        uint32_t sb = smb + (uint32_t)stage * STG_B;
#pragma unroll
        for (int i = 0; i < 2; i++)
            cp16(sb + (uint32_t)aRow[i] * 80 + aSeg[i] * 2,
                 A + (size_t)(m0 + aRow[i]) * K + kb + aSeg[i]);
#pragma unroll
        for (int i = 0; i < 2; i++)
            cp16(sb + 10240 + (uint32_t)bRow[i] * 272 + bSeg[i] * 2,
                 W + (size_t)(kb + bRow[i]) * N + n0 + bSeg[i]);
        cp_commit();
    };

    int ntiles = K / 32;
    cpTile(0, 0);
    if (ntiles > 1) cpTile(1, 32);

    for (int kt = 0; kt < ntiles; kt++) {
        if (kt + 2 < ntiles) { cpTile((kt + 2) & 3, (kt + 2) * 32); cp_wait2(); }
        else if (kt + 1 < ntiles) cp_wait1();
        else cp_wait0();
        __syncthreads();

        uint32_t so = (uint32_t)(kt & 3) * STG_B;
#pragma unroll
        for (int q = 0; q < 2; q++) {
            int kq = q * 16;
            uint32_t af[4][4], bu0[4], bu1[4];
#pragma unroll
            for (int mt = 0; mt < 4; mt++) ldsm_x4(a_addr[mt] + so + kq * 2, af[mt]);
            ldsm_x4_t(b_addr[0] + so + kq * 272, bu0);
            ldsm_x4_t(b_addr[1] + so + kq * 272, bu1);
#pragma unroll
            for (int mt = 0; mt < 4; mt++) {
                mma_f16(acc[mt][0], af[mt], bu0 + 0);
                mma_f16(acc[mt][1], af[mt], bu0 + 2);
                mma_f16(acc[mt][2], af[mt], bu1 + 0);
                mma_f16(acc[mt][3], af[mt], bu1 + 2);
            }
        }
    }

#pragma unroll
    for (int mt = 0; mt < 4; mt++) {
        int r0 = m0 + wm + mt * 16 + gid;
#pragma unroll
        for (int nt = 0; nt < 4; nt++) {
            int c = n0 + wn + nt * 8 + tig * 2;
            float b0v = bias[c], b1v = bias[c + 1];
            float e00 = acc[mt][nt][0] + b0v, e01 = acc[mt][nt][1] + b1v;
            float e10 = acc[mt][nt][2] + b0v, e11 = acc[mt][nt][3] + b1v;
            if constexpr (BLEND) {
                float2 x0 = h2f2(*(const uint32_t*)(bld + (size_t)r0 * N + c));
                float2 x1 = h2f2(*(const uint32_t*)(bld + (size_t)(r0 + 8) * N + c));
                e00 = x0.x * wa + e00 * wb; e01 = x0.y * wa + e01 * wb;
                e10 = x1.x * wa + e10 * wb; e11 = x1.y * wa + e11 * wb;
            }
            if constexpr (sizeof(TO) == 2) {
                *(uint32_t*)((__half*)C + (size_t)r0 * N + c) = packh2(e00, e01);
                *(uint32_t*)((__half*)C + (size_t)(r0 + 8) * N + c) = packh2(e10, e11);
            } else {
                float2 v0, v1;
                v0.x = e00; v0.y = e01; v1.x = e10; v1.y = e11;
                *(float2*)((float*)C + (size_t)r0 * N + c) = v0;
                *(float2*)((float*)C + (size_t)(r0 + 8) * N + c) = v1;
            }
        }
    }
}

// ---------------- modulation (smem-tiled): sigmoid(hs@Wg + bg + cvec@Wa + ba) ----------------
__global__ __launch_bounds__(256) void gatemod2(
    const float* __restrict__ hs, const float* __restrict__ Wg,
    const float* __restrict__ bg, const float* __restrict__ cvec,
    const float* __restrict__ Wa, const float* __restrict__ ba,
    float* __restrict__ MODo)
{
    __shared__ float Wgs[64][16];
    __shared__ float hss[16][68];
    __shared__ float awS[16];

    int tid = threadIdx.x;
    int m0 = blockIdx.x * 16;
    int r = tid >> 4, n = tid & 15;

    if (tid < 16) {
        float aw = ba[tid] + bg[tid];
#pragma unroll
        for (int k = 0; k < 16; k++) aw += cvec[k] * Wa[k * 16 + tid];
        awS[tid] = aw;
    }

    float acc = 0.f;
    for (int kt = 0; kt < H; kt += 64) {
        __syncthreads();
        *(float4*)&((float*)Wgs)[tid * 4] = *(const float4*)&Wg[kt * 16 + tid * 4];
        int r2 = tid >> 4, k2 = (tid & 15) * 4;
        *(float4*)&hss[r2][k2] = *(const float4*)&hs[(size_t)(m0 + r2) * H + kt + k2];
        __syncthreads();
#pragma unroll
        for (int k = 0; k < 64; k++) acc += hss[r][k] * Wgs[k][n];
    }
    float x = acc + awS[n];
    MODo[(size_t)(m0 + r) * NH + n] = 1.f / (1.f + __expf(-x));
}

// ---------------- main attention (fp16 TC): 16 heads, hd=64, half out ----------------
__global__ __launch_bounds__(256) void attn_main_f16(
    const __half* __restrict__ Qb, const __half* __restrict__ Kb,
    const __half* __restrict__ Vb, const float* __restrict__ MODb,
    const int* __restrict__ maskb, __half* __restrict__ Ob)
{
    __shared__ __half Ks[32][72];   // [key][d], 144B stride
    __shared__ __half Vs[32][72];
    __shared__ float Madd[32];

    int tid = threadIdx.x, lane = tid & 31, warp = tid >> 5;
    int gid = lane >> 2, tig = lane & 3;
    int q0 = blockIdx.x * 128, h = blockIdx.y, b = blockIdx.z;
    int qw = q0 + warp * 16;

    uint32_t qf[4][4];
    const __half* Qg = Qb + (size_t)(b * S + qw) * H + h * HD;
#pragma unroll
    for (int s = 0; s < 4; s++) {
        int c0 = s * 16 + 2 * tig;
        qf[s][0] = *(const uint32_t*)(Qg + (size_t)gid * H + c0);
        qf[s][1] = *(const uint32_t*)(Qg + (size_t)(gid + 8) * H + c0);
        qf[s][2] = *(const uint32_t*)(Qg + (size_t)gid * H + c0 + 8);
        qf[s][3] = *(const uint32_t*)(Qg + (size_t)(gid + 8) * H + c0 + 8);
    }
    float mod0 = MODb[(size_t)(b * S + qw + gid) * NH + h] * 0.125f;
    float mod1 = MODb[(size_t)(b * S + qw + gid + 8) * NH + h] * 0.125f;

    uint32_t kaddr[2], vaddr[4];
#pragma unroll
    for (int ntp = 0; ntp < 2; ntp++)
        kaddr[ntp] = cvta_s(&Ks[(ntp * 2 + (lane >> 4)) * 8 + (lane & 7)][((lane >> 3) & 1) * 8]);
#pragma unroll
    for (int nfp = 0; nfp < 4; nfp++)
        vaddr[nfp] = cvta_s(&Vs[((lane >> 3) & 1) * 8 + (lane & 7)][(nfp * 2 + (lane >> 4)) * 8]);

    int cr = tid >> 3, cs = (tid & 7) * 8;
    const __half* KgB = Kb + (size_t)(b * S) * H + h * HD;
    const __half* VgB = Vb + (size_t)(b * S) * H + h * HD;

    float m0v = -1e30f, m1v = -1e30f, l0 = 0.f, l1 = 0.f;
    float oacc[8][4];
#pragma unroll
    for (int nf = 0; nf < 8; nf++)
#pragma unroll
        for (int r = 0; r < 4; r++) oacc[nf][r] = 0.f;

    for (int kt = 0; kt < S; kt += 32) {
        __syncthreads();
        *(uint4*)&Ks[cr][cs] = *(const uint4*)(KgB + (size_t)(kt + cr) * H + cs);
        *(uint4*)&Vs[cr][cs] = *(const uint4*)(VgB + (size_t)(kt + cr) * H + cs);
        if (tid < 32) Madd[tid] = maskb[b * S + kt + tid] ? 0.f : -1e30f;
        __syncthreads();

        float sc[4][4];
#pragma unroll
        for (int nf = 0; nf < 4; nf++)
#pragma unroll
            for (int r = 0; r < 4; r++) sc[nf][r] = 0.f;
#pragma unroll
        for (int s = 0; s < 4; s++) {
            uint32_t ku0[4], ku1[4];
            ldsm_x4(kaddr[0] + s * 32, ku0);
            ldsm_x4(kaddr[1] + s * 32, ku1);
            mma_f16(sc[0], qf[s], ku0 + 0);
            mma_f16(sc[1], qf[s], ku0 + 2);
            mma_f16(sc[2], qf[s], ku1 + 0);
            mma_f16(sc[3], qf[s], ku1 + 2);
        }

        float mx0 = -1e30f, mx1 = -1e30f;
#pragma unroll
        for (int nf = 0; nf < 4; nf++) {
            float ma = Madd[nf * 8 + 2 * tig], mb2 = Madd[nf * 8 + 2 * tig + 1];
            sc[nf][0] = sc[nf][0] * mod0 + ma;
            sc[nf][1] = sc[nf][1] * mod0 + mb2;
            sc[nf][2] = sc[nf][2] * mod1 + ma;
            sc[nf][3] = sc[nf][3] * mod1 + mb2;
            mx0 = fmaxf(mx0, fmaxf(sc[nf][0], sc[nf][1]));
            mx1 = fmaxf(mx1, fmaxf(sc[nf][2], sc[nf][3]));
        }
        mx0 = fmaxf(mx0, __shfl_xor_sync(0xffffffffu, mx0, 1));
        mx0 = fmaxf(mx0, __shfl_xor_sync(0xffffffffu, mx0, 2));
        mx1 = fmaxf(mx1, __shfl_xor_sync(0xffffffffu, mx1, 1));
        mx1 = fmaxf(mx1, __shfl_xor_sync(0xffffffffu, mx1, 2));
        float mn0 = fmaxf(m0v, mx0), mn1 = fmaxf(m1v, mx1);
        float al0 = __expf(m0v - mn0), al1 = __expf(m1v - mn1);
        float ps0 = 0.f, ps1 = 0.f;
        uint32_t pva[2][4];
#pragma unroll
        for (int nf = 0; nf < 4; nf++) {
            float p00 = __expf(sc[nf][0] - mn0), p01 = __expf(sc[nf][1] - mn0);
            float p10 = __expf(sc[nf][2] - mn1), p11 = __expf(sc[nf][3] - mn1);
            ps0 += p00 + p01; ps1 += p10 + p11;
            int s2 = nf >> 1, hi = (nf & 1) * 2;
            pva[s2][hi]     = packh2(p00, p01);
            pva[s2][hi + 1] = packh2(p10, p11);
        }
        ps0 += __shfl_xor_sync(0xffffffffu, ps0, 1);
        ps0 += __shfl_xor_sync(0xffffffffu, ps0, 2);
        ps1 += __shfl_xor_sync(0xffffffffu, ps1, 1);
        ps1 += __shfl_xor_sync(0xffffffffu, ps1, 2);
        l0 = l0 * al0 + ps0; l1 = l1 * al1 + ps1;
        m0v = mn0; m1v = mn1;
#pragma unroll
        for (int nf = 0; nf < 8; nf++) {
            oacc[nf][0] *= al0; oacc[nf][1] *= al0;
            oacc[nf][2] *= al1; oacc[nf][3] *= al1;
        }

#pragma unroll
        for (int s2 = 0; s2 < 2; s2++) {
#pragma unroll
            for (int nfp = 0; nfp < 4; nfp++) {
                uint32_t vu[4];
                ldsm_x4_t(vaddr[nfp] + s2 * 16 * 144, vu);
                mma_f16(oacc[nfp * 2],     pva[s2], vu + 0);
                mma_f16(oacc[nfp * 2 + 1], pva[s2], vu + 2);
            }
        }
    }

    float inv0 = 1.f / l0, inv1 = 1.f / l1;
    __half* Og = Ob + (size_t)(b * S + qw) * H + h * HD;
#pragma unroll
    for (int nf = 0; nf < 8; nf++) {
        int c = nf * 8 + 2 * tig;
        *(uint32_t*)(Og + (size_t)gid * H + c) =
            packh2(oacc[nf][0] * inv0, oacc[nf][1] * inv0);
        *(uint32_t*)(Og + (size_t)(gid + 8) * H + c) =
            packh2(oacc[nf][2] * inv1, oacc[nf][3] * inv1);
    }
}

// ---------------- big-head attention (fp16 TC): 4 heads, hd=256, 64q/512t ----------------
__global__ __launch_bounds__(512) void attn_big_f16(
    const __half* __restrict__ Qb, const __half* __restrict__ Kb,
    const __half* __restrict__ Vb, int ld, __half* __restrict__ Ob, float scale)
{
    __shared__ __half Ks[32][264];   // [key][d], 528B stride
    __shared__ __half Vs[32][264];
    __shared__ float SP[64][36];
    __shared__ __half SPh[64][40];
    __shared__ float Mst[64], Lst[64], Alp[64];

    int tid = threadIdx.x, lane = tid & 31, warp = tid >> 5;
    int gid = lane >> 2, tig = lane & 3;
    int wm = warp >> 2, wn = warp & 3;
    int q0 = blockIdx.x * 64, h = blockIdx.y, b = blockIdx.z;

    uint32_t qf[16][4];
    const __half* Qg = Qb + (size_t)(b * S + q0 + wm * 16) * ld + h * BD;
#pragma unroll
    for (int s = 0; s < 16; s++) {
        int c0 = s * 16 + 2 * tig;
        qf[s][0] = *(const uint32_t*)(Qg + (size_t)gid * ld + c0);
        qf[s][1] = *(const uint32_t*)(Qg + (size_t)(gid + 8) * ld + c0);
        qf[s][2] = *(const uint32_t*)(Qg + (size_t)gid * ld + c0 + 8);
        qf[s][3] = *(const uint32_t*)(Qg + (size_t)(gid + 8) * ld + c0 + 8);
    }
    if (tid < 64) { Mst[tid] = -1e30f; Lst[tid] = 0.f; }

    uint32_t kaddr = cvta_s(&Ks[wn * 8 + (lane & 7)][((lane >> 3) & 1) * 8]);
    uint32_t paddr = cvta_s(&SPh[wm * 16 + ((lane >> 3) & 1) * 8 + (lane & 7)][(lane >> 4) * 8]);
    uint32_t vaddr = cvta_s(&Vs[((lane >> 3) & 1) * 8 + (lane & 7)][wn * 64 + (lane >> 4) * 8]);

    const __half* KgB = Kb + (size_t)(b * S) * ld + h * BD;
    const __half* VgB = Vb + (size_t)(b * S) * ld + h * BD;

    float oacc[8][4];
#pragma unroll
    for (int nf = 0; nf < 8; nf++)
#pragma unroll
        for (int r = 0; r < 4; r++) oacc[nf][r] = 0.f;

    for (int kt = 0; kt < S; kt += 32) {
        __syncthreads();
#pragma unroll
        for (int it = 0; it < 2; it++) {
            int idx = tid + it * 512;
            int r = idx >> 5, sg = (idx & 31) * 8;
            *(uint4*)&Ks[r][sg] = *(const uint4*)(KgB + (size_t)(kt + r) * ld + sg);
            *(uint4*)&Vs[r][sg] = *(const uint4*)(VgB + (size_t)(kt + r) * ld + sg);
        }
        __syncthreads();

        float sc[4] = {0.f, 0.f, 0.f, 0.f};
#pragma unroll
        for (int s = 0; s < 16; s++) {
            uint32_t ku[2];
            ldsm_x2(kaddr + s * 32, ku);
            mma_f16(sc, qf[s], ku);
        }
        {
            int rw = wm * 16 + gid, c = wn * 8 + 2 * tig;
            float2 v;
            v.x = sc[0] * scale; v.y = sc[1] * scale;
            *(float2*)&SP[rw][c] = v;
            v.x = sc[2] * scale; v.y = sc[3] * scale;
            *(float2*)&SP[rw + 8][c] = v;
        }
        __syncthreads();

        {
            int row = tid >> 3, c0 = (tid & 7) * 4;
            float4 sv = *(const float4*)&SP[row][c0];
            float mx = fmaxf(fmaxf(sv.x, sv.y), fmaxf(sv.z, sv.w));
            mx = fmaxf(mx, __shfl_xor_sync(0xffffffffu, mx, 1));
            mx = fmaxf(mx, __shfl_xor_sync(0xffffffffu, mx, 2));
            mx = fmaxf(mx, __shfl_xor_sync(0xffffffffu, mx, 4));
            float mold = Mst[row];
            float mnew = fmaxf(mold, mx);
            float p0 = __expf(sv.x - mnew), p1 = __expf(sv.y - mnew);
            float p2 = __expf(sv.z - mnew), p3 = __expf(sv.w - mnew);
            float ps = p0 + p1 + p2 + p3;
            ps += __shfl_xor_sync(0xffffffffu, ps, 1);
            ps += __shfl_xor_sync(0xffffffffu, ps, 2);
            ps += __shfl_xor_sync(0xffffffffu, ps, 4);
            if ((tid & 7) == 0) {
                float al = __expf(mold - mnew);
                Mst[row] = mnew; Lst[row] = Lst[row] * al + ps; Alp[row] = al;
            }
            uint2 pu; pu.x = packh2(p0, p1); pu.y = packh2(p2, p3);
            *(uint2*)&SPh[row][c0] = pu;
        }
        __syncthreads();

        float al0 = Alp[wm * 16 + gid], al1 = Alp[wm * 16 + gid + 8];
#pragma unroll
        for (int nf = 0; nf < 8; nf++) {
            oacc[nf][0] *= al0; oacc[nf][1] *= al0;
            oacc[nf][2] *= al1; oacc[nf][3] *= al1;
        }

#pragma unroll
        for (int s2 = 0; s2 < 2; s2++) {
            uint32_t pa[4];
            ldsm_x4(paddr + s2 * 32, pa);
#pragma unroll
            for (int nfp = 0; nfp < 4; nfp++) {
                uint32_t vu[4];
                ldsm_x4_t(vaddr + s2 * 8448 + nfp * 32, vu);
                mma_f16(oacc[nfp * 2],     pa, vu + 0);
                mma_f16(oacc[nfp * 2 + 1], pa, vu + 2);
            }
        }
    }

    float inv0 = 1.f / Lst[wm * 16 + gid], inv1 = 1.f / Lst[wm * 16 + gid + 8];
    __half* Og = Ob + (size_t)(b * S + q0 + wm * 16) * H + h * BD;
#pragma unroll
    for (int nf = 0; nf < 8; nf++) {
        int c = wn * 64 + nf * 8 + 2 * tig;
        *(uint32_t*)(Og + (size_t)gid * H + c) =
            packh2(oacc[nf][0] * inv0, oacc[nf][1] * inv0);
        *(uint32_t*)(Og + (size_t)(gid + 8) * H + c) =
            packh2(oacc[nf][2] * inv1, oacc[nf][3] * inv1);
    }
}

// ---------------- launch ----------------
#define GEMM_SMEM 75776

extern "C" void kernel_launch(void* const* d_in, const int* in_sizes, int n_in,
                              void* d_out, int out_size)
{
    (void)in_sizes; (void)n_in; (void)out_size;
    const float* hs      = (const float*)d_in[0];
    const int*   mask    = (const int*)  d_in[1];
    const float* cvec    = (const float*)d_in[2];
    const float* Wq      = (const float*)d_in[3];
    const float* bq      = (const float*)d_in[4];
    const float* Wk      = (const float*)d_in[5];
    const float* bk      = (const float*)d_in[6];
    const float* Wv      = (const float*)d_in[7];
    const float* bv      = (const float*)d_in[8];
    const float* Wg      = (const float*)d_in[9];
    const float* bg      = (const float*)d_in[10];
    const float* Wa      = (const float*)d_in[11];
    const float* ba      = (const float*)d_in[12];
    const float* ca_in_w = (const float*)d_in[13];
    const float* ca_in_b = (const float*)d_in[14];
    const float* ca_ow   = (const float*)d_in[15];
    const float* ca_ob   = (const float*)d_in[16];
    const float* ma_in_w = (const float*)d_in[17];
    const float* ma_in_b = (const float*)d_in[18];
    const float* ma_ow   = (const float*)d_in[19];
    const float* ma_ob   = (const float*)d_in[20];
    const float* Wo      = (const float*)d_in[21];
    const float* bo      = (const float*)d_in[22];

    __half *Q, *K, *V, *QKV3, *T1, *HSh, *WH, *CTX;
    float *MOD;
    cudaGetSymbolAddress((void**)&Q, g_Q);
    cudaGetSymbolAddress((void**)&K, g_K);
    cudaGetSymbolAddress((void**)&V, g_V);
    cudaGetSymbolAddress((void**)&MOD, g_MOD);
    cudaGetSymbolAddress((void**)&CTX, g_CTX);
    cudaGetSymbolAddress((void**)&QKV3, g_QKV3);
    cudaGetSymbolAddress((void**)&T1, g_T1);
    cudaGetSymbolAddress((void**)&HSh, g_HSh);
    cudaGetSymbolAddress((void**)&WH, g_WH);

    // half-weight pool offsets
    __half* WqH = WH + 0 * (size_t)MHH;
    __half* WkH = WH + 1 * (size_t)MHH;
    __half* WvH = WH + 2 * (size_t)MHH;
    __half* caInH = WH + 3 * (size_t)MHH;    // 3 MHH
    __half* caOwH = WH + 6 * (size_t)MHH;
    __half* maInH = WH + 7 * (size_t)MHH;    // 3 MHH
    __half* maOwH = WH + 10 * (size_t)MHH;
    __half* WoH = WH + 11 * (size_t)MHH;

    cudaFuncSetAttribute(gemm_tc<__half, false>, cudaFuncAttributeMaxDynamicSharedMemorySize, GEMM_SMEM);
    cudaFuncSetAttribute(gemm_tc<__half, true>,  cudaFuncAttributeMaxDynamicSharedMemorySize, GEMM_SMEM);
    cudaFuncSetAttribute(gemm_tc<float, false>,  cudaFuncAttributeMaxDynamicSharedMemorySize, GEMM_SMEM);

    // converts (8 elems/thread, 2048 elems/block)
    cvt_h<<<MS * H / 2048, 256>>>(hs, HSh, MS * H);
    cvt_h<<<MHH / 2048, 256>>>(Wq, WqH, MHH);
    cvt_h<<<MHH / 2048, 256>>>(Wk, WkH, MHH);
    cvt_h<<<MHH / 2048, 256>>>(Wv, WvH, MHH);
    cvt_h<<<3 * MHH / 2048, 256>>>(ca_in_w, caInH, 3 * MHH);
    cvt_h<<<MHH / 2048, 256>>>(ca_ow, caOwH, MHH);
    cvt_h<<<3 * MHH / 2048, 256>>>(ma_in_w, maInH, 3 * MHH);
    cvt_h<<<MHH / 2048, 256>>>(ma_ow, maOwH, MHH);
    cvt_h<<<MHH / 2048, 256>>>(Wo, WoH, MHH);

    dim3 gN1(H / 128, MS / 128);
    dim3 gN3(3 * H / 128, MS / 128);

    // main attention path
    gemm_tc<__half, false><<<gN1, 256, GEMM_SMEM>>>(HSh, WqH, bq, Q, MS, H, H, nullptr, 0.f, 0.f);
    gemm_tc<__half, false><<<gN1, 256, GEMM_SMEM>>>(HSh, WkH, bk, K, MS, H, H, nullptr, 0.f, 0.f);
    gemm_tc<__half, false><<<gN1, 256, GEMM_SMEM>>>(HSh, WvH, bv, V, MS, H, H, nullptr, 0.f, 0.f);
    gatemod2<<<MS / 16, 256>>>(hs, Wg, bg, cvec, Wa, ba, MOD);
    attn_main_f16<<<dim3(S / 128, NH, B), 256>>>(Q, K, V, MOD, mask, CTX);

    // causal branch (blend fused into out-proj epilogue; CTX half)
    gemm_tc<__half, false><<<gN3, 256, GEMM_SMEM>>>(HSh, caInH, ca_in_b, QKV3, MS, 3 * H, H, nullptr, 0.f, 0.f);
    attn_big_f16<<<dim3(S / 64, BH, B), 512>>>(QKV3, QKV3 + H, QKV3 + 2 * H, 3 * H, T1, 0.0625f);
    gemm_tc<__half, true><<<gN1, 256, GEMM_SMEM>>>(T1, caOwH, ca_ob, CTX, MS, H, H, CTX, 0.3f, 0.7f);

    // metacognitive branch (blend fused)
    gemm_tc<__half, false><<<gN3, 256, GEMM_SMEM>>>(CTX, maInH, ma_in_b, QKV3, MS, 3 * H, H, nullptr, 0.f, 0.f);
    attn_big_f16<<<dim3(S / 64, BH, B), 512>>>(QKV3, QKV3 + H, QKV3 + 2 * H, 3 * H, T1, 0.0625f);
    gemm_tc<__half, true><<<gN1, 256, GEMM_SMEM>>>(T1, maOwH, ma_ob, CTX, MS, H, H, CTX, 0.85f, 0.15f);

    // output projection
    gemm_tc<float, false><<<gN1, 256, GEMM_SMEM>>>(CTX, WoH, bo, (float*)d_out, MS, H, H, nullptr, 0.f, 0.f);
}